// round 9
// baseline (speedup 1.0000x reference)
#include <cuda_runtime.h>
#include <cuda_bf16.h>
#include <cuda_fp16.h>
#include <cstdint>
#include <math.h>

// Problem constants
#define N_ENT 100000
#define N_REL 1000
#define RANK  256
#define TWO_R 512
#define BATCH 1024
#define MAX_NB 50

// Output layout (flattened tuple): scores, n_lhs, n_rel, n_rhs, n_gec
#define OFF_SCORES 0
#define OFF_NLHS   ((size_t)BATCH * N_ENT)
#define OFF_NREL   (OFF_NLHS + (size_t)BATCH * RANK)
#define OFF_NRHS   (OFF_NREL + (size_t)BATCH * RANK)
#define OFF_NGEC   (OFF_NRHS + (size_t)BATCH * RANK)

// Power-of-2 scaling for fp16 GEMM (exact, no extra rounding)
#define SCALE_Q 1048576.0f            // 2^20
#define SCALE_E 1024.0f               // 2^10
#define SCALE_OUT 9.313225746154785e-10f   // 2^-30

// E conversion work distribution: 51.2M floats in units of 1024 floats
#define CONV_UNITS 50000
// k1: every 119th block real; k2: every 11th; k3a: every 40th
#define K1_STRIDE 119
#define K1_GRID   (256 * K1_STRIDE)     // 30464 (256 real, 30208 conv)
#define K2_STRIDE 11
#define K2_GRID   (1024 * K2_STRIDE)    // 11264 (1024 real, 10240 conv)
#define K3_STRIDE 40
#define K3_GRID   (256 * K3_STRIDE)     // 10240 (256 real, 9984 conv)
#define CONV_OFF_K2 30208
#define CONV_OFF_K3 40448

// Scratch (static device globals; no allocation allowed)
__device__ float g_w0 [BATCH * RANK];
__device__ float g_w1 [BATCH * RANK];
__device__ float g_ec0[BATCH * RANK];
__device__ float g_ec1[BATCH * RANK];
__device__ float g_en0[BATCH * RANK];
__device__ float g_en1[BATCH * RANK];

// scaled fp16 operands for the big GEMM
__device__ __half g_Qf[BATCH * TWO_R];
__device__ __half g_Ef[(size_t)N_ENT * TWO_R];

// ===========================================================================
// PTX helpers (compute_103-safe subset: cp.async / ldmatrix / mma.sync only)
// ===========================================================================
__device__ __forceinline__ uint32_t smem_to_u32(const void* smem_ptr) {
    uint32_t addr;
    asm("{ .reg .u64 tmp; cvta.to.shared.u64 tmp, %1; cvt.u32.u64 %0, tmp; }"
        : "=r"(addr) : "l"(smem_ptr));
    return addr;
}

#define CP_ASYNC16(smem_u32, gptr) \
    asm volatile("cp.async.cg.shared.global [%0], [%1], 16;" \
        :: "r"(smem_u32), "l"(gptr) : "memory")

#define CP_ASYNC_COMMIT() \
    asm volatile("cp.async.commit_group;" ::: "memory")

#define CP_ASYNC_WAIT_GROUP(n) \
    asm volatile("cp.async.wait_group %0;" :: "n"(n) : "memory")

__device__ __forceinline__ void ldsm_x4(uint32_t r[4], uint32_t addr) {
    asm volatile("ldmatrix.sync.aligned.m8n8.x4.shared.b16 {%0,%1,%2,%3}, [%4];"
        : "=r"(r[0]), "=r"(r[1]), "=r"(r[2]), "=r"(r[3]) : "r"(addr));
}

__device__ __forceinline__ void mma_16816_f16(
    float c[4], const uint32_t a[4], uint32_t b0, uint32_t b1)
{
    asm volatile(
        "mma.sync.aligned.m16n8k16.row.col.f32.f16.f16.f32 "
        "{%0,%1,%2,%3}, {%4,%5,%6,%7}, {%8,%9}, {%0,%1,%2,%3};"
        : "+f"(c[0]), "+f"(c[1]), "+f"(c[2]), "+f"(c[3])
        : "r"(a[0]), "r"(a[1]), "r"(a[2]), "r"(a[3]), "r"(b0), "r"(b1));
}

// ---------------------------------------------------------------------------
// E->fp16 conversion slice: unit u converts floats [u*1024, (u+1)*1024)
// (one full block of 256 threads, 4 floats each)
// ---------------------------------------------------------------------------
__device__ __forceinline__ void conv_unit(const float* __restrict__ E, int u, int tid)
{
    if (u >= CONV_UNITS) return;
    const size_t i = ((size_t)u * 256 + tid) * 4;
    const float4 v = *(const float4*)(E + i);
    __half2* p = (__half2*)(g_Ef + i);
    p[0] = __floats2half2_rn(v.x * SCALE_E, v.y * SCALE_E);
    p[1] = __floats2half2_rn(v.z * SCALE_E, v.w * SCALE_E);
}

// ---------------------------------------------------------------------------
// K1: w0/w1 = t0@W0 - t1@W1 + bw0 ; t0@W1 + t1@W0 + bw1   (4 rows/block)
// Interleaved with E-conversion blocks (bid % K1_STRIDE != 0).
// ---------------------------------------------------------------------------
#define K1_ROWS 4
__global__ __launch_bounds__(256) void k1_wproj(
    const int* __restrict__ x,
    const float* __restrict__ E_ent, const float* __restrict__ E_rel,
    const float* __restrict__ W0, const float* __restrict__ W1,
    const float* __restrict__ bw0, const float* __restrict__ bw1)
{
    const int bid = blockIdx.x;
    const int tid = threadIdx.x;
    if (bid % K1_STRIDE != 0) {
        conv_unit(E_ent, bid - bid / K1_STRIDE - 1, tid);
        return;
    }
    const int b0 = (bid / K1_STRIDE) * K1_ROWS;

    __shared__ float t0s[K1_ROWS][TWO_R];
    __shared__ float t1s[K1_ROWS][TWO_R];

    for (int rr = 0; rr < K1_ROWS; rr++) {
        const int b = b0 + rr;
        const size_t lhs = (size_t)x[b * 3 + 0];
        const size_t rel = (size_t)x[b * 3 + 1];
        const float* lrow = E_ent + lhs * TWO_R;
        const float* rrow = E_rel + rel * TWO_R;
        for (int j = tid; j < TWO_R; j += 256) {
            if (j < RANK) {
                t0s[rr][j] = lrow[j];
                t1s[rr][j] = lrow[RANK + j];
            } else {
                t0s[rr][j] = rrow[j - RANK];
                t1s[rr][j] = rrow[RANK + (j - RANK)];
            }
        }
    }
    __syncthreads();

    const int k = tid;
    float a0[K1_ROWS], a1[K1_ROWS];
#pragma unroll
    for (int rr = 0; rr < K1_ROWS; rr++) { a0[rr] = 0.f; a1[rr] = 0.f; }

#pragma unroll 8
    for (int j = 0; j < TWO_R; j++) {
        const float w0jk = W0[j * RANK + k];
        const float w1jk = W1[j * RANK + k];
#pragma unroll
        for (int rr = 0; rr < K1_ROWS; rr++) {
            const float a = t0s[rr][j];
            const float c = t1s[rr][j];
            a0[rr] += a * w0jk - c * w1jk;
            a1[rr] += a * w1jk + c * w0jk;
        }
    }
    const float b0k = bw0[k], b1k = bw1[k];
#pragma unroll
    for (int rr = 0; rr < K1_ROWS; rr++) {
        g_w0[(b0 + rr) * RANK + k] = a0[rr] + b0k;
        g_w1[(b0 + rr) * RANK + k] = a1[rr] + b1k;
    }
}

// ---------------------------------------------------------------------------
// K2: logits over 50 neighbors, softmax, ec0/ec1 weighted sums.
// Neighbor rows staged once into dynamic smem (100 KB) via cp.async.
// Interleaved with E-conversion blocks.
// ---------------------------------------------------------------------------
#define K2_SMEM (MAX_NB * TWO_R * 4)   // 102400
__global__ __launch_bounds__(256) void k2_attn(
    const int* __restrict__ nb_idx, const float* __restrict__ E_ent)
{
    const int bid = blockIdx.x;
    const int tid = threadIdx.x;
    if (bid % K2_STRIDE != 0) {
        conv_unit(E_ent, CONV_OFF_K2 + bid - bid / K2_STRIDE - 1, tid);
        return;
    }
    const int b = bid / K2_STRIDE;

    extern __shared__ __align__(16) float nbs[];   // [MAX_NB][TWO_R]
    __shared__ float w0s[RANK], w1s[RANK];
    __shared__ float logit_s[MAX_NB];
    __shared__ float alpha_s[MAX_NB];
    __shared__ int   idx_s[MAX_NB];

    const int wid = tid >> 5;
    const int lane = tid & 31;

    w0s[tid] = g_w0[b * RANK + tid];
    w1s[tid] = g_w1[b * RANK + tid];
    if (tid < MAX_NB) idx_s[tid] = nb_idx[b * MAX_NB + tid];
    __syncthreads();

    const uint32_t nbs_u = smem_to_u32(nbs);
    for (int u = tid; u < MAX_NB * 128; u += 256) {
        const int m = u >> 7;
        const int q = u & 127;
        CP_ASYNC16(nbs_u + (uint32_t)u * 16,
                   E_ent + (size_t)idx_s[m] * TWO_R + q * 4);
    }
    CP_ASYNC_COMMIT();
    CP_ASYNC_WAIT_GROUP(0);
    __syncthreads();

    for (int m = wid; m < MAX_NB; m += 8) {
        const float* row = nbs + m * TWO_R;
        float s = 0.f;
#pragma unroll
        for (int k = lane; k < RANK; k += 32)
            s += w0s[k] * row[k] - w1s[k] * row[RANK + k];
#pragma unroll
        for (int o = 16; o > 0; o >>= 1) s += __shfl_xor_sync(0xffffffffu, s, o);
        if (lane == 0) logit_s[m] = s;
    }
    __syncthreads();

    if (tid == 0) {
        float mx = logit_s[0];
        for (int m = 1; m < MAX_NB; m++) mx = fmaxf(mx, logit_s[m]);
        float sum = 0.f;
        for (int m = 0; m < MAX_NB; m++) { float e = __expf(logit_s[m] - mx); alpha_s[m] = e; sum += e; }
        const float inv = 1.0f / sum;
        for (int m = 0; m < MAX_NB; m++) alpha_s[m] *= inv;
    }
    __syncthreads();

    const int k = tid;
    float acc0 = 0.f, acc1 = 0.f;
#pragma unroll 10
    for (int m = 0; m < MAX_NB; m++) {
        const float a = alpha_s[m];
        acc0 += a * nbs[m * TWO_R + k];
        acc1 += a * nbs[m * TWO_R + RANK + k];
    }
    g_ec0[b * RANK + k] = acc0;
    g_ec1[b * RANK + k] = acc1;
}

// ---------------------------------------------------------------------------
// K3a: ec0n/ec1n complex projection by W20/W21, 4 rows/block.
// Interleaved with E-conversion blocks.
// ---------------------------------------------------------------------------
#define K3_ROWS 4
__global__ __launch_bounds__(256) void k3a_ecproj(
    const float* __restrict__ E_ent,
    const float* __restrict__ W20, const float* __restrict__ W21,
    const float* __restrict__ bw20, const float* __restrict__ bw21)
{
    const int bid = blockIdx.x;
    const int tid = threadIdx.x;
    if (bid % K3_STRIDE != 0) {
        conv_unit(E_ent, CONV_OFF_K3 + bid - bid / K3_STRIDE - 1, tid);
        return;
    }
    const int b0 = (bid / K3_STRIDE) * K3_ROWS;

    __shared__ float e0s[K3_ROWS][RANK];
    __shared__ float e1s[K3_ROWS][RANK];

    for (int rr = 0; rr < K3_ROWS; rr++) {
        e0s[rr][tid] = g_ec0[(b0 + rr) * RANK + tid];
        e1s[rr][tid] = g_ec1[(b0 + rr) * RANK + tid];
    }
    __syncthreads();

    const int k = tid;
    float a0[K3_ROWS], a1[K3_ROWS];
#pragma unroll
    for (int rr = 0; rr < K3_ROWS; rr++) { a0[rr] = 0.f; a1[rr] = 0.f; }

#pragma unroll 8
    for (int j = 0; j < RANK; j++) {
        const float w20 = W20[j * RANK + k];
        const float w21 = W21[j * RANK + k];
#pragma unroll
        for (int rr = 0; rr < K3_ROWS; rr++) {
            const float a = e0s[rr][j];
            const float c = e1s[rr][j];
            a0[rr] += a * w20 - c * w21;
            a1[rr] += a * w21 + c * w20;
        }
    }
    const float b20 = bw20[k], b21 = bw21[k];
#pragma unroll
    for (int rr = 0; rr < K3_ROWS; rr++) {
        g_en0[(b0 + rr) * RANK + k] = a0[rr] + b20;
        g_en1[(b0 + rr) * RANK + k] = a1[rr] + b21;
    }
}

// ---------------------------------------------------------------------------
// K3b: gate scalar, gec, q_re/q_im (scaled fp16 into g_Qf), norms
// ---------------------------------------------------------------------------
__global__ __launch_bounds__(256) void k3b_gate_q(
    const int* __restrict__ x,
    const float* __restrict__ E_ent, const float* __restrict__ E_rel,
    const float* __restrict__ Uo0, const float* __restrict__ Uo1,
    const float* __restrict__ Wo0, const float* __restrict__ b_g,
    float* __restrict__ out)
{
    __shared__ float warp_part[8];
    __shared__ float g_sh;
    const int b = blockIdx.x;
    const int k = threadIdx.x;
    const int wid = k >> 5, lane = k & 31;

    const size_t lhs = (size_t)x[b * 3 + 0];
    const size_t rel = (size_t)x[b * 3 + 1];
    const size_t rhs = (size_t)x[b * 3 + 2];

    const float l0 = E_ent[lhs * TWO_R + k];
    const float l1 = E_ent[lhs * TWO_R + RANK + k];
    const float r0 = E_rel[rel * TWO_R + k];
    const float r1 = E_rel[rel * TWO_R + RANK + k];
    const float o0 = E_ent[rhs * TWO_R + k];
    const float o1 = E_ent[rhs * TWO_R + RANK + k];

    const float en0 = g_en0[b * RANK + k];
    const float en1 = g_en1[b * RANK + k];

    const float sr = l0 * r0 - l1 * r1;
    const float si = l1 * r0 + l0 * r1;

    float p = sr * Uo0[k] - si * Uo1[k] + en0 * Wo0[k];
#pragma unroll
    for (int o = 16; o > 0; o >>= 1) p += __shfl_xor_sync(0xffffffffu, p, o);
    if (lane == 0) warp_part[wid] = p;
    __syncthreads();
    if (k == 0) {
        float tot = 0.f;
#pragma unroll
        for (int w = 0; w < 8; w++) tot += warp_part[w];
        tot += b_g[0];
        g_sh = 1.0f / (1.0f + __expf(-tot));
    }
    __syncthreads();
    const float g = g_sh;

    const float gec0 = g * en0 + (1.0f - g);
    const float gec1 = g * en1;

    const float q_re = sr * gec0 + si * gec1;
    const float q_im = si * gec0 - sr * gec1;

    g_Qf[b * TWO_R + k]        = __float2half_rn(q_re * SCALE_Q);
    g_Qf[b * TWO_R + RANK + k] = __float2half_rn(q_im * SCALE_Q);

    const size_t nk = (size_t)b * RANK + k;
    out[OFF_NLHS + nk] = sqrtf(l0 * l0 + l1 * l1);
    out[OFF_NREL + nk] = sqrtf(r0 * r0 + r1 * r1);
    out[OFF_NRHS + nk] = sqrtf(o0 * o0 + o1 * o1);
    out[OFF_NGEC + nk] = sqrtf(gec0 * gec0 + gec1 * gec1);
}

// ---------------------------------------------------------------------------
// K4: scores = Qf (1024x512) @ Ef^T (512x100000), single scaled-fp16 GEMM on
// mma.sync.m16n8k16. Persistent CTAs, continuous cp.async chunk stream,
// 4-stage pipeline with 3-chunk lookahead (wait_group(2)).
// ---------------------------------------------------------------------------
#define NCHUNK 8
#define NTILE_M (BATCH / 128)                 // 8
#define NTILE_N ((N_ENT + 255) / 256)         // 391
#define NTILES  (NTILE_M * NTILE_N)           // 3128
#define ROW_B    144                   // 128B data + 16B pad
#define A_TILE_B (128 * ROW_B)         // 18432
#define B_TILE_B (256 * ROW_B)         // 36864
#define STAGE_B  (A_TILE_B + B_TILE_B) // 55296
#define NSTAGE   4
#define SMEM_K4  (NSTAGE * STAGE_B)    // 221184
#define K4_THREADS 256

// Issue loads for global stream position p (tile = own-tile p>>3, chunk p&7)
__device__ __forceinline__ void k4_load_pos(
    uint32_t sbase, int p, int stg, int bidx, int gridx,
    const __half* Qf, const __half* Ef, int tid)
{
    const int T = bidx + (p >> 3) * gridx;
    const int chunk = p & 7;
    const int m0 = (T & (NTILE_M - 1)) * 128;
    const int n0 = (T / NTILE_M) * 256;
    const int k0 = chunk * 64;
    const uint32_t sb = sbase + (uint32_t)stg * STAGE_B;
    // A tile: 128 rows x 8 x 16B = 1024 transfers
#pragma unroll
    for (int u = 0; u < 4; u++) {
        const int idx = tid + u * K4_THREADS;   // 0..1023
        const int row = idx >> 3;
        const int g   = idx & 7;
        const uint32_t soff = sb + (uint32_t)(row * ROW_B + g * 16);
        CP_ASYNC16(soff, Qf + (size_t)(m0 + row) * TWO_R + k0 + g * 8);
    }
    // B tile: 256 rows x 8 x 16B = 2048 transfers
#pragma unroll
    for (int u = 0; u < 8; u++) {
        const int idx = tid + u * K4_THREADS;   // 0..2047
        const int row = idx >> 3;
        const int g   = idx & 7;
        int er = n0 + row; if (er >= N_ENT) er = N_ENT - 1;
        const uint32_t soff = sb + (uint32_t)(A_TILE_B + row * ROW_B + g * 16);
        CP_ASYNC16(soff, Ef + (size_t)er * TWO_R + k0 + g * 8);
    }
}

__global__ __launch_bounds__(K4_THREADS, 1) void k4_hmma(
    const __half* __restrict__ Qf, const __half* __restrict__ Ef,
    float* __restrict__ C)
{
    extern __shared__ __align__(1024) char smem[];
    const uint32_t sbase = smem_to_u32(smem);
    const int tid  = threadIdx.x;
    const int wid  = tid >> 5;
    const int lane = tid & 31;
    const int wm   = wid & 1;       // 0..1 -> 64-row slice
    const int wn   = wid >> 1;      // 0..3 -> 64-col slice
    const int bidx = blockIdx.x;
    const int gridx = gridDim.x;

    const int ntiles_own = (NTILES - bidx + gridx - 1) / gridx;
    const int pmax = ntiles_own * NCHUNK;

    const int laneRow = ((lane >> 3) & 1) * 8 + (lane & 7);
    const int laneG   = lane >> 4;
    const int rowAbase = wm * 64 + laneRow;
    const int rowBbase = wn * 64 + laneRow;

    // preload stream positions 0,1,2 into stages 0,1,2
    k4_load_pos(sbase, 0, 0, bidx, gridx, Qf, Ef, tid);
    CP_ASYNC_COMMIT();
    k4_load_pos(sbase, 1, 1, bidx, gridx, Qf, Ef, tid);
    CP_ASYNC_COMMIT();
    k4_load_pos(sbase, 2, 2, bidx, gridx, Qf, Ef, tid);
    CP_ASYNC_COMMIT();

    int p_load = 3;
    int stg_load = 3;
    int stg = 0;

#pragma unroll 1
    for (int j = 0; j < ntiles_own; j++) {
        const int T = bidx + j * gridx;
        const int m0 = (T & (NTILE_M - 1)) * 128;
        const int n0 = (T / NTILE_M) * 256;

        float acc[4][8][4];
#pragma unroll
        for (int a = 0; a < 4; a++)
#pragma unroll
            for (int b = 0; b < 8; b++)
#pragma unroll
                for (int c = 0; c < 4; c++) acc[a][b][c] = 0.f;

#pragma unroll 1
        for (int i = 0; i < NCHUNK; i++) {
            CP_ASYNC_WAIT_GROUP(2);
            __syncthreads();

            if (p_load < pmax)
                k4_load_pos(sbase, p_load, stg_load, bidx, gridx, Qf, Ef, tid);
            CP_ASYNC_COMMIT();
            p_load++;
            stg_load = (stg_load + 1) & (NSTAGE - 1);

            const uint32_t sA = sbase + (uint32_t)stg * STAGE_B;
            const uint32_t sB = sA + A_TILE_B;

#pragma unroll
            for (int kh = 0; kh < 4; kh++) {
                const uint32_t gof = (uint32_t)(kh * 32 + laneG * 16);

                uint32_t a_op[4][4], b_op[4][4];
#pragma unroll
                for (int mt = 0; mt < 4; mt++)
                    ldsm_x4(a_op[mt], sA + (uint32_t)((rowAbase + mt * 16) * ROW_B) + gof);
#pragma unroll
                for (int q = 0; q < 4; q++)
                    ldsm_x4(b_op[q], sB + (uint32_t)((rowBbase + q * 16) * ROW_B) + gof);

#pragma unroll
                for (int mt = 0; mt < 4; mt++)
#pragma unroll
                    for (int jj = 0; jj < 8; jj++)
                        mma_16816_f16(acc[mt][jj], a_op[mt],
                                      b_op[jj >> 1][jj & 1], b_op[jj >> 1][2 + (jj & 1)]);
            }

            stg = (stg + 1) & (NSTAGE - 1);
        }

        // Epilogue (overlaps with next tile's in-flight cp.async loads)
        const int erow = (lane >> 2);
        const int ecol = (lane & 3) * 2;
#pragma unroll
        for (int mt = 0; mt < 4; mt++) {
            const int r1 = m0 + wm * 64 + mt * 16 + erow;
#pragma unroll
            for (int jj = 0; jj < 8; jj++) {
                const int n = n0 + wn * 64 + jj * 8 + ecol;
                if (n < N_ENT) {
                    float2 v01 = make_float2(acc[mt][jj][0] * SCALE_OUT,
                                             acc[mt][jj][1] * SCALE_OUT);
                    float2 v23 = make_float2(acc[mt][jj][2] * SCALE_OUT,
                                             acc[mt][jj][3] * SCALE_OUT);
                    *(float2*)(C + (size_t)r1 * N_ENT + n) = v01;
                    *(float2*)(C + (size_t)(r1 + 8) * N_ENT + n) = v23;
                }
            }
        }
    }
}

// ---------------------------------------------------------------------------
extern "C" void kernel_launch(void* const* d_in, const int* in_sizes, int n_in,
                              void* d_out, int out_size)
{
    const int*   x      = (const int*)  d_in[0];
    const int*   nb_idx = (const int*)  d_in[1];
    const float* E_ent  = (const float*)d_in[2];
    const float* E_rel  = (const float*)d_in[3];
    const float* W0     = (const float*)d_in[4];
    const float* W1     = (const float*)d_in[5];
    const float* bw0    = (const float*)d_in[6];
    const float* bw1    = (const float*)d_in[7];
    const float* W20    = (const float*)d_in[8];
    const float* W21    = (const float*)d_in[9];
    const float* bw20   = (const float*)d_in[10];
    const float* bw21   = (const float*)d_in[11];
    const float* Uo0    = (const float*)d_in[12];
    const float* Uo1    = (const float*)d_in[13];
    const float* Wo0    = (const float*)d_in[14];
    const float* b_g    = (const float*)d_in[15];
    float* out = (float*)d_out;

    __half *Qf, *Ef;
    cudaGetSymbolAddress((void**)&Qf, g_Qf);
    cudaGetSymbolAddress((void**)&Ef, g_Ef);

    cudaFuncSetAttribute(k4_hmma, cudaFuncAttributeMaxDynamicSharedMemorySize, SMEM_K4);
    cudaFuncSetAttribute(k2_attn, cudaFuncAttributeMaxDynamicSharedMemorySize, K2_SMEM);

    int nsm = 148;
    cudaDeviceGetAttribute(&nsm, cudaDevAttrMultiProcessorCount, 0);

    // E-conversion distributed across k1/k2/k3a as interleaved extra blocks
    k1_wproj  <<<K1_GRID, 256>>>(x, E_ent, E_rel, W0, W1, bw0, bw1);
    k2_attn   <<<K2_GRID, 256, K2_SMEM>>>(nb_idx, E_ent);
    k3a_ecproj<<<K3_GRID, 256>>>(E_ent, W20, W21, bw20, bw21);
    k3b_gate_q<<<BATCH, 256>>>(x, E_ent, E_rel, Uo0, Uo1, Wo0, b_g, out);

    k4_hmma<<<nsm, K4_THREADS, SMEM_K4>>>(Qf, Ef, out + OFF_SCORES);
}

// round 10
// speedup vs baseline: 1.0014x; 1.0014x over previous
#include <cuda_runtime.h>
#include <cuda_bf16.h>
#include <cuda_fp16.h>
#include <cstdint>
#include <math.h>

// Problem constants
#define N_ENT 100000
#define N_REL 1000
#define RANK  256
#define TWO_R 512
#define BATCH 1024
#define MAX_NB 50

// Output layout (flattened tuple): scores, n_lhs, n_rel, n_rhs, n_gec
#define OFF_SCORES 0
#define OFF_NLHS   ((size_t)BATCH * N_ENT)
#define OFF_NREL   (OFF_NLHS + (size_t)BATCH * RANK)
#define OFF_NRHS   (OFF_NREL + (size_t)BATCH * RANK)
#define OFF_NGEC   (OFF_NRHS + (size_t)BATCH * RANK)

// Power-of-2 scaling for fp16 GEMM (exact, no extra rounding)
#define SCALE_Q 1048576.0f            // 2^20
#define SCALE_E 1024.0f               // 2^10
#define SCALE_OUT 9.313225746154785e-10f   // 2^-30

// Scratch (static device globals; no allocation allowed)
__device__ float g_w0 [BATCH * RANK];
__device__ float g_w1 [BATCH * RANK];
__device__ float g_ec0[BATCH * RANK];
__device__ float g_ec1[BATCH * RANK];
__device__ float g_en0[BATCH * RANK];
__device__ float g_en1[BATCH * RANK];

// scaled fp16 operands for the big GEMM
__device__ __half g_Qf[BATCH * TWO_R];
__device__ __half g_Ef[(size_t)N_ENT * TWO_R];

// ===========================================================================
// Side stream + fork/join events, created at static-init time (before the
// harness's memory checkpoint; no device allocation inside kernel_launch).
// ===========================================================================
struct StreamHolder {
    cudaStream_t s;
    cudaEvent_t fork, join;
    StreamHolder() {
        cudaStreamCreateWithFlags(&s, cudaStreamNonBlocking);
        cudaEventCreateWithFlags(&fork, cudaEventDisableTiming);
        cudaEventCreateWithFlags(&join, cudaEventDisableTiming);
    }
};
static StreamHolder g_sh;

// ===========================================================================
// PTX helpers (compute_103-safe subset: cp.async / ldmatrix / mma.sync only)
// ===========================================================================
__device__ __forceinline__ uint32_t smem_to_u32(const void* smem_ptr) {
    uint32_t addr;
    asm("{ .reg .u64 tmp; cvta.to.shared.u64 tmp, %1; cvt.u32.u64 %0, tmp; }"
        : "=r"(addr) : "l"(smem_ptr));
    return addr;
}

#define CP_ASYNC16(smem_u32, gptr) \
    asm volatile("cp.async.cg.shared.global [%0], [%1], 16;" \
        :: "r"(smem_u32), "l"(gptr) : "memory")

#define CP_ASYNC_COMMIT() \
    asm volatile("cp.async.commit_group;" ::: "memory")

#define CP_ASYNC_WAIT_GROUP(n) \
    asm volatile("cp.async.wait_group %0;" :: "n"(n) : "memory")

__device__ __forceinline__ void ldsm_x4(uint32_t r[4], uint32_t addr) {
    asm volatile("ldmatrix.sync.aligned.m8n8.x4.shared.b16 {%0,%1,%2,%3}, [%4];"
        : "=r"(r[0]), "=r"(r[1]), "=r"(r[2]), "=r"(r[3]) : "r"(addr));
}

__device__ __forceinline__ void mma_16816_f16(
    float c[4], const uint32_t a[4], uint32_t b0, uint32_t b1)
{
    asm volatile(
        "mma.sync.aligned.m16n8k16.row.col.f32.f16.f16.f32 "
        "{%0,%1,%2,%3}, {%4,%5,%6,%7}, {%8,%9}, {%0,%1,%2,%3};"
        : "+f"(c[0]), "+f"(c[1]), "+f"(c[2]), "+f"(c[3])
        : "r"(a[0]), "r"(a[1]), "r"(a[2]), "r"(a[3]), "r"(b0), "r"(b1));
}

// ---------------------------------------------------------------------------
// K0: convert E_ent (fp32) into scaled fp16  (runs on side stream)
// ---------------------------------------------------------------------------
__global__ __launch_bounds__(256) void k0_cvtE(const float* __restrict__ E)
{
    const size_t i = ((size_t)blockIdx.x * 256 + threadIdx.x) * 4;
    const float4 v = *(const float4*)(E + i);
    __half2* p = (__half2*)(g_Ef + i);
    p[0] = __floats2half2_rn(v.x * SCALE_E, v.y * SCALE_E);
    p[1] = __floats2half2_rn(v.z * SCALE_E, v.w * SCALE_E);
}

// ---------------------------------------------------------------------------
// K1: w0/w1 = t0@W0 - t1@W1 + bw0 ; t0@W1 + t1@W0 + bw1   (4 rows/block)
// ---------------------------------------------------------------------------
#define K1_ROWS 4
__global__ __launch_bounds__(256) void k1_wproj(
    const int* __restrict__ x,
    const float* __restrict__ E_ent, const float* __restrict__ E_rel,
    const float* __restrict__ W0, const float* __restrict__ W1,
    const float* __restrict__ bw0, const float* __restrict__ bw1)
{
    __shared__ float t0s[K1_ROWS][TWO_R];
    __shared__ float t1s[K1_ROWS][TWO_R];
    const int b0 = blockIdx.x * K1_ROWS;
    const int tid = threadIdx.x;

    for (int rr = 0; rr < K1_ROWS; rr++) {
        const int b = b0 + rr;
        const size_t lhs = (size_t)x[b * 3 + 0];
        const size_t rel = (size_t)x[b * 3 + 1];
        const float* lrow = E_ent + lhs * TWO_R;
        const float* rrow = E_rel + rel * TWO_R;
        for (int j = tid; j < TWO_R; j += 256) {
            if (j < RANK) {
                t0s[rr][j] = lrow[j];
                t1s[rr][j] = lrow[RANK + j];
            } else {
                t0s[rr][j] = rrow[j - RANK];
                t1s[rr][j] = rrow[RANK + (j - RANK)];
            }
        }
    }
    __syncthreads();

    const int k = tid;
    float a0[K1_ROWS], a1[K1_ROWS];
#pragma unroll
    for (int rr = 0; rr < K1_ROWS; rr++) { a0[rr] = 0.f; a1[rr] = 0.f; }

#pragma unroll 8
    for (int j = 0; j < TWO_R; j++) {
        const float w0jk = W0[j * RANK + k];
        const float w1jk = W1[j * RANK + k];
#pragma unroll
        for (int rr = 0; rr < K1_ROWS; rr++) {
            const float a = t0s[rr][j];
            const float c = t1s[rr][j];
            a0[rr] += a * w0jk - c * w1jk;
            a1[rr] += a * w1jk + c * w0jk;
        }
    }
    const float b0k = bw0[k], b1k = bw1[k];
#pragma unroll
    for (int rr = 0; rr < K1_ROWS; rr++) {
        g_w0[(b0 + rr) * RANK + k] = a0[rr] + b0k;
        g_w1[(b0 + rr) * RANK + k] = a1[rr] + b1k;
    }
}

// ---------------------------------------------------------------------------
// K2: logits over 50 neighbors, softmax, ec0/ec1 weighted sums.
// Neighbor rows staged once into dynamic smem (100 KB) via cp.async.
// ---------------------------------------------------------------------------
#define K2_SMEM (MAX_NB * TWO_R * 4)   // 102400
__global__ __launch_bounds__(256) void k2_attn(
    const int* __restrict__ nb_idx, const float* __restrict__ E_ent)
{
    extern __shared__ __align__(16) float nbs[];   // [MAX_NB][TWO_R]
    __shared__ float w0s[RANK], w1s[RANK];
    __shared__ float logit_s[MAX_NB];
    __shared__ float alpha_s[MAX_NB];
    __shared__ int   idx_s[MAX_NB];

    const int b = blockIdx.x;
    const int tid = threadIdx.x;
    const int wid = tid >> 5;
    const int lane = tid & 31;

    w0s[tid] = g_w0[b * RANK + tid];
    w1s[tid] = g_w1[b * RANK + tid];
    if (tid < MAX_NB) idx_s[tid] = nb_idx[b * MAX_NB + tid];
    __syncthreads();

    const uint32_t nbs_u = smem_to_u32(nbs);
    for (int u = tid; u < MAX_NB * 128; u += 256) {
        const int m = u >> 7;
        const int q = u & 127;
        CP_ASYNC16(nbs_u + (uint32_t)u * 16,
                   E_ent + (size_t)idx_s[m] * TWO_R + q * 4);
    }
    CP_ASYNC_COMMIT();
    CP_ASYNC_WAIT_GROUP(0);
    __syncthreads();

    for (int m = wid; m < MAX_NB; m += 8) {
        const float* row = nbs + m * TWO_R;
        float s = 0.f;
#pragma unroll
        for (int k = lane; k < RANK; k += 32)
            s += w0s[k] * row[k] - w1s[k] * row[RANK + k];
#pragma unroll
        for (int o = 16; o > 0; o >>= 1) s += __shfl_xor_sync(0xffffffffu, s, o);
        if (lane == 0) logit_s[m] = s;
    }
    __syncthreads();

    if (tid == 0) {
        float mx = logit_s[0];
        for (int m = 1; m < MAX_NB; m++) mx = fmaxf(mx, logit_s[m]);
        float sum = 0.f;
        for (int m = 0; m < MAX_NB; m++) { float e = __expf(logit_s[m] - mx); alpha_s[m] = e; sum += e; }
        const float inv = 1.0f / sum;
        for (int m = 0; m < MAX_NB; m++) alpha_s[m] *= inv;
    }
    __syncthreads();

    const int k = tid;
    float acc0 = 0.f, acc1 = 0.f;
#pragma unroll 10
    for (int m = 0; m < MAX_NB; m++) {
        const float a = alpha_s[m];
        acc0 += a * nbs[m * TWO_R + k];
        acc1 += a * nbs[m * TWO_R + RANK + k];
    }
    g_ec0[b * RANK + k] = acc0;
    g_ec1[b * RANK + k] = acc1;
}

// ---------------------------------------------------------------------------
// K3a: ec0n/ec1n complex projection by W20/W21, 4 rows/block
// ---------------------------------------------------------------------------
#define K3_ROWS 4
__global__ __launch_bounds__(256) void k3a_ecproj(
    const float* __restrict__ W20, const float* __restrict__ W21,
    const float* __restrict__ bw20, const float* __restrict__ bw21)
{
    __shared__ float e0s[K3_ROWS][RANK];
    __shared__ float e1s[K3_ROWS][RANK];
    const int b0 = blockIdx.x * K3_ROWS;
    const int tid = threadIdx.x;

    for (int rr = 0; rr < K3_ROWS; rr++) {
        e0s[rr][tid] = g_ec0[(b0 + rr) * RANK + tid];
        e1s[rr][tid] = g_ec1[(b0 + rr) * RANK + tid];
    }
    __syncthreads();

    const int k = tid;
    float a0[K3_ROWS], a1[K3_ROWS];
#pragma unroll
    for (int rr = 0; rr < K3_ROWS; rr++) { a0[rr] = 0.f; a1[rr] = 0.f; }

#pragma unroll 8
    for (int j = 0; j < RANK; j++) {
        const float w20 = W20[j * RANK + k];
        const float w21 = W21[j * RANK + k];
#pragma unroll
        for (int rr = 0; rr < K3_ROWS; rr++) {
            const float a = e0s[rr][j];
            const float c = e1s[rr][j];
            a0[rr] += a * w20 - c * w21;
            a1[rr] += a * w21 + c * w20;
        }
    }
    const float b20 = bw20[k], b21 = bw21[k];
#pragma unroll
    for (int rr = 0; rr < K3_ROWS; rr++) {
        g_en0[(b0 + rr) * RANK + k] = a0[rr] + b20;
        g_en1[(b0 + rr) * RANK + k] = a1[rr] + b21;
    }
}

// ---------------------------------------------------------------------------
// K3b: gate scalar, gec, q_re/q_im (scaled fp16 into g_Qf), norms
// ---------------------------------------------------------------------------
__global__ __launch_bounds__(256) void k3b_gate_q(
    const int* __restrict__ x,
    const float* __restrict__ E_ent, const float* __restrict__ E_rel,
    const float* __restrict__ Uo0, const float* __restrict__ Uo1,
    const float* __restrict__ Wo0, const float* __restrict__ b_g,
    float* __restrict__ out)
{
    __shared__ float warp_part[8];
    __shared__ float g_sh2;
    const int b = blockIdx.x;
    const int k = threadIdx.x;
    const int wid = k >> 5, lane = k & 31;

    const size_t lhs = (size_t)x[b * 3 + 0];
    const size_t rel = (size_t)x[b * 3 + 1];
    const size_t rhs = (size_t)x[b * 3 + 2];

    const float l0 = E_ent[lhs * TWO_R + k];
    const float l1 = E_ent[lhs * TWO_R + RANK + k];
    const float r0 = E_rel[rel * TWO_R + k];
    const float r1 = E_rel[rel * TWO_R + RANK + k];
    const float o0 = E_ent[rhs * TWO_R + k];
    const float o1 = E_ent[rhs * TWO_R + RANK + k];

    const float en0 = g_en0[b * RANK + k];
    const float en1 = g_en1[b * RANK + k];

    const float sr = l0 * r0 - l1 * r1;
    const float si = l1 * r0 + l0 * r1;

    float p = sr * Uo0[k] - si * Uo1[k] + en0 * Wo0[k];
#pragma unroll
    for (int o = 16; o > 0; o >>= 1) p += __shfl_xor_sync(0xffffffffu, p, o);
    if (lane == 0) warp_part[wid] = p;
    __syncthreads();
    if (k == 0) {
        float tot = 0.f;
#pragma unroll
        for (int w = 0; w < 8; w++) tot += warp_part[w];
        tot += b_g[0];
        g_sh2 = 1.0f / (1.0f + __expf(-tot));
    }
    __syncthreads();
    const float g = g_sh2;

    const float gec0 = g * en0 + (1.0f - g);
    const float gec1 = g * en1;

    const float q_re = sr * gec0 + si * gec1;
    const float q_im = si * gec0 - sr * gec1;

    g_Qf[b * TWO_R + k]        = __float2half_rn(q_re * SCALE_Q);
    g_Qf[b * TWO_R + RANK + k] = __float2half_rn(q_im * SCALE_Q);

    const size_t nk = (size_t)b * RANK + k;
    out[OFF_NLHS + nk] = sqrtf(l0 * l0 + l1 * l1);
    out[OFF_NREL + nk] = sqrtf(r0 * r0 + r1 * r1);
    out[OFF_NRHS + nk] = sqrtf(o0 * o0 + o1 * o1);
    out[OFF_NGEC + nk] = sqrtf(gec0 * gec0 + gec1 * gec1);
}

// ---------------------------------------------------------------------------
// K4: scores = Qf (1024x512) @ Ef^T (512x100000), single scaled-fp16 GEMM on
// mma.sync.m16n8k16. Persistent CTAs, continuous cp.async chunk stream,
// 3-stage pipeline, wait_group(1) (R8-proven configuration).
// ---------------------------------------------------------------------------
#define NCHUNK 8
#define NTILE_M (BATCH / 128)                 // 8
#define NTILE_N ((N_ENT + 255) / 256)         // 391
#define NTILES  (NTILE_M * NTILE_N)           // 3128
#define ROW_B    144                   // 128B data + 16B pad
#define A_TILE_B (128 * ROW_B)         // 18432
#define B_TILE_B (256 * ROW_B)         // 36864
#define STAGE_B  (A_TILE_B + B_TILE_B) // 55296
#define NSTAGE   3
#define SMEM_K4  (NSTAGE * STAGE_B)    // 165888
#define K4_THREADS 256

// Issue loads for global stream position p (tile = own-tile p>>3, chunk p&7)
__device__ __forceinline__ void k4_load_pos(
    uint32_t sbase, int p, int stg, int bidx, int gridx,
    const __half* Qf, const __half* Ef, int tid)
{
    const int T = bidx + (p >> 3) * gridx;
    const int chunk = p & 7;
    const int m0 = (T & (NTILE_M - 1)) * 128;
    const int n0 = (T / NTILE_M) * 256;
    const int k0 = chunk * 64;
    const uint32_t sb = sbase + (uint32_t)stg * STAGE_B;
    // A tile: 128 rows x 8 x 16B = 1024 transfers
#pragma unroll
    for (int u = 0; u < 4; u++) {
        const int idx = tid + u * K4_THREADS;   // 0..1023
        const int row = idx >> 3;
        const int g   = idx & 7;
        const uint32_t soff = sb + (uint32_t)(row * ROW_B + g * 16);
        CP_ASYNC16(soff, Qf + (size_t)(m0 + row) * TWO_R + k0 + g * 8);
    }
    // B tile: 256 rows x 8 x 16B = 2048 transfers
#pragma unroll
    for (int u = 0; u < 8; u++) {
        const int idx = tid + u * K4_THREADS;   // 0..2047
        const int row = idx >> 3;
        const int g   = idx & 7;
        int er = n0 + row; if (er >= N_ENT) er = N_ENT - 1;
        const uint32_t soff = sb + (uint32_t)(A_TILE_B + row * ROW_B + g * 16);
        CP_ASYNC16(soff, Ef + (size_t)er * TWO_R + k0 + g * 8);
    }
}

__global__ __launch_bounds__(K4_THREADS, 1) void k4_hmma(
    const __half* __restrict__ Qf, const __half* __restrict__ Ef,
    float* __restrict__ C)
{
    extern __shared__ __align__(1024) char smem[];
    const uint32_t sbase = smem_to_u32(smem);
    const int tid  = threadIdx.x;
    const int wid  = tid >> 5;
    const int lane = tid & 31;
    const int wm   = wid & 1;       // 0..1 -> 64-row slice
    const int wn   = wid >> 1;      // 0..3 -> 64-col slice
    const int bidx = blockIdx.x;
    const int gridx = gridDim.x;

    const int ntiles_own = (NTILES - bidx + gridx - 1) / gridx;
    const int pmax = ntiles_own * NCHUNK;

    const int laneRow = ((lane >> 3) & 1) * 8 + (lane & 7);
    const int laneG   = lane >> 4;
    const int rowAbase = wm * 64 + laneRow;
    const int rowBbase = wn * 64 + laneRow;

    // preload stream positions 0 and 1
    k4_load_pos(sbase, 0, 0, bidx, gridx, Qf, Ef, tid);
    CP_ASYNC_COMMIT();
    if (pmax > 1) k4_load_pos(sbase, 1, 1, bidx, gridx, Qf, Ef, tid);
    CP_ASYNC_COMMIT();

    int p_load = 2;
    int stg_load = 2;
    int stg = 0;

#pragma unroll 1
    for (int j = 0; j < ntiles_own; j++) {
        const int T = bidx + j * gridx;
        const int m0 = (T & (NTILE_M - 1)) * 128;
        const int n0 = (T / NTILE_M) * 256;

        float acc[4][8][4];
#pragma unroll
        for (int a = 0; a < 4; a++)
#pragma unroll
            for (int b = 0; b < 8; b++)
#pragma unroll
                for (int c = 0; c < 4; c++) acc[a][b][c] = 0.f;

#pragma unroll 1
        for (int i = 0; i < NCHUNK; i++) {
            CP_ASYNC_WAIT_GROUP(1);
            __syncthreads();

            if (p_load < pmax)
                k4_load_pos(sbase, p_load, stg_load, bidx, gridx, Qf, Ef, tid);
            CP_ASYNC_COMMIT();
            p_load++;
            stg_load = stg_load + 1; if (stg_load >= NSTAGE) stg_load = 0;

            const uint32_t sA = sbase + (uint32_t)stg * STAGE_B;
            const uint32_t sB = sA + A_TILE_B;

#pragma unroll
            for (int kh = 0; kh < 4; kh++) {
                const uint32_t gof = (uint32_t)(kh * 32 + laneG * 16);

                uint32_t a_op[4][4], b_op[4][4];
#pragma unroll
                for (int mt = 0; mt < 4; mt++)
                    ldsm_x4(a_op[mt], sA + (uint32_t)((rowAbase + mt * 16) * ROW_B) + gof);
#pragma unroll
                for (int q = 0; q < 4; q++)
                    ldsm_x4(b_op[q], sB + (uint32_t)((rowBbase + q * 16) * ROW_B) + gof);

#pragma unroll
                for (int mt = 0; mt < 4; mt++)
#pragma unroll
                    for (int jj = 0; jj < 8; jj++)
                        mma_16816_f16(acc[mt][jj], a_op[mt],
                                      b_op[jj >> 1][jj & 1], b_op[jj >> 1][2 + (jj & 1)]);
            }

            stg = stg + 1; if (stg >= NSTAGE) stg = 0;
        }

        // Epilogue (overlaps with next tile's in-flight cp.async loads)
        const int erow = (lane >> 2);
        const int ecol = (lane & 3) * 2;
#pragma unroll
        for (int mt = 0; mt < 4; mt++) {
            const int r1 = m0 + wm * 64 + mt * 16 + erow;
#pragma unroll
            for (int jj = 0; jj < 8; jj++) {
                const int n = n0 + wn * 64 + jj * 8 + ecol;
                if (n < N_ENT) {
                    float2 v01 = make_float2(acc[mt][jj][0] * SCALE_OUT,
                                             acc[mt][jj][1] * SCALE_OUT);
                    float2 v23 = make_float2(acc[mt][jj][2] * SCALE_OUT,
                                             acc[mt][jj][3] * SCALE_OUT);
                    *(float2*)(C + (size_t)r1 * N_ENT + n) = v01;
                    *(float2*)(C + (size_t)(r1 + 8) * N_ENT + n) = v23;
                }
            }
        }
    }
}

// ---------------------------------------------------------------------------
extern "C" void kernel_launch(void* const* d_in, const int* in_sizes, int n_in,
                              void* d_out, int out_size)
{
    const int*   x      = (const int*)  d_in[0];
    const int*   nb_idx = (const int*)  d_in[1];
    const float* E_ent  = (const float*)d_in[2];
    const float* E_rel  = (const float*)d_in[3];
    const float* W0     = (const float*)d_in[4];
    const float* W1     = (const float*)d_in[5];
    const float* bw0    = (const float*)d_in[6];
    const float* bw1    = (const float*)d_in[7];
    const float* W20    = (const float*)d_in[8];
    const float* W21    = (const float*)d_in[9];
    const float* bw20   = (const float*)d_in[10];
    const float* bw21   = (const float*)d_in[11];
    const float* Uo0    = (const float*)d_in[12];
    const float* Uo1    = (const float*)d_in[13];
    const float* Wo0    = (const float*)d_in[14];
    const float* b_g    = (const float*)d_in[15];
    float* out = (float*)d_out;

    __half *Qf, *Ef;
    cudaGetSymbolAddress((void**)&Qf, g_Qf);
    cudaGetSymbolAddress((void**)&Ef, g_Ef);

    cudaFuncSetAttribute(k4_hmma, cudaFuncAttributeMaxDynamicSharedMemorySize, SMEM_K4);
    cudaFuncSetAttribute(k2_attn, cudaFuncAttributeMaxDynamicSharedMemorySize, K2_SMEM);

    int nsm = 148;
    cudaDeviceGetAttribute(&nsm, cudaDevAttrMultiProcessorCount, 0);

    const cudaStream_t ms = cudaStreamPerThread;   // the captured stream

    // Fork: E->fp16 conversion runs on the side stream, concurrent with the
    // latency-bound aux chain on the main stream.
    cudaEventRecord(g_sh.fork, ms);
    cudaStreamWaitEvent(g_sh.s, g_sh.fork, 0);
    k0_cvtE<<<50000, 256, 0, g_sh.s>>>(E_ent);
    cudaEventRecord(g_sh.join, g_sh.s);

    // Aux chain on the main stream
    k1_wproj  <<<BATCH / K1_ROWS, 256, 0, ms>>>(x, E_ent, E_rel, W0, W1, bw0, bw1);
    k2_attn   <<<BATCH, 256, K2_SMEM, ms>>>(nb_idx, E_ent);
    k3a_ecproj<<<BATCH / K3_ROWS, 256, 0, ms>>>(W20, W21, bw20, bw21);
    k3b_gate_q<<<BATCH, 256, 0, ms>>>(x, E_ent, E_rel, Uo0, Uo1, Wo0, b_g, out);

    // Join: k4 needs both g_Ef (side stream) and g_Qf (main chain)
    cudaStreamWaitEvent(ms, g_sh.join, 0);
    k4_hmma<<<nsm, K4_THREADS, SMEM_K4, ms>>>(Qf, Ef, out + OFF_SCORES);
}

// round 12
// speedup vs baseline: 1.1249x; 1.1233x over previous
#include <cuda_runtime.h>
#include <cuda_bf16.h>
#include <cuda_fp16.h>
#include <cstdint>
#include <math.h>

// Problem constants
#define N_ENT 100000
#define N_REL 1000
#define RANK  256
#define TWO_R 512
#define BATCH 1024
#define MAX_NB 50

// Output layout (flattened tuple): scores, n_lhs, n_rel, n_rhs, n_gec
#define OFF_SCORES 0
#define OFF_NLHS   ((size_t)BATCH * N_ENT)
#define OFF_NREL   (OFF_NLHS + (size_t)BATCH * RANK)
#define OFF_NRHS   (OFF_NREL + (size_t)BATCH * RANK)
#define OFF_NGEC   (OFF_NRHS + (size_t)BATCH * RANK)

// Power-of-2 scaling for fp16 GEMM (exact, no extra rounding)
#define SCALE_Q 1048576.0f            // 2^20
#define SCALE_E 1024.0f               // 2^10
#define SCALE_OUT 9.313225746154785e-10f   // 2^-30

#define BR (BATCH * RANK)

// Scratch (static device globals; no allocation allowed)
// w and en are SPLIT-K partial buffers (combined by the consumer kernels)
__device__ float g_w0 [2 * BR];
__device__ float g_w1 [2 * BR];
__device__ float g_ec0[BR];
__device__ float g_ec1[BR];
__device__ float g_en0[4 * BR];
__device__ float g_en1[4 * BR];

// scaled fp16 operands for the big GEMM
__device__ __half g_Qf[BATCH * TWO_R];
__device__ __half g_Ef[(size_t)N_ENT * TWO_R];

// ===========================================================================
// PTX helpers (compute_103-safe subset: cp.async / ldmatrix / mma.sync only)
// ===========================================================================
__device__ __forceinline__ uint32_t smem_to_u32(const void* smem_ptr) {
    uint32_t addr;
    asm("{ .reg .u64 tmp; cvta.to.shared.u64 tmp, %1; cvt.u32.u64 %0, tmp; }"
        : "=r"(addr) : "l"(smem_ptr));
    return addr;
}

#define CP_ASYNC16(smem_u32, gptr) \
    asm volatile("cp.async.cg.shared.global [%0], [%1], 16;" \
        :: "r"(smem_u32), "l"(gptr) : "memory")

#define CP_ASYNC_COMMIT() \
    asm volatile("cp.async.commit_group;" ::: "memory")

#define CP_ASYNC_WAIT_GROUP(n) \
    asm volatile("cp.async.wait_group %0;" :: "n"(n) : "memory")

__device__ __forceinline__ void ldsm_x4(uint32_t r[4], uint32_t addr) {
    asm volatile("ldmatrix.sync.aligned.m8n8.x4.shared.b16 {%0,%1,%2,%3}, [%4];"
        : "=r"(r[0]), "=r"(r[1]), "=r"(r[2]), "=r"(r[3]) : "r"(addr));
}

__device__ __forceinline__ void mma_16816_f16(
    float c[4], const uint32_t a[4], uint32_t b0, uint32_t b1)
{
    asm volatile(
        "mma.sync.aligned.m16n8k16.row.col.f32.f16.f16.f32 "
        "{%0,%1,%2,%3}, {%4,%5,%6,%7}, {%8,%9}, {%0,%1,%2,%3};"
        : "+f"(c[0]), "+f"(c[1]), "+f"(c[2]), "+f"(c[3])
        : "r"(a[0]), "r"(a[1]), "r"(a[2]), "r"(a[3]), "r"(b0), "r"(b1));
}

// ---------------------------------------------------------------------------
// K0: convert E_ent (fp32) into scaled fp16
// ---------------------------------------------------------------------------
__global__ __launch_bounds__(256) void k0_cvtE(const float* __restrict__ E)
{
    const size_t i = ((size_t)blockIdx.x * 256 + threadIdx.x) * 4;
    const float4 v = *(const float4*)(E + i);
    __half2* p = (__half2*)(g_Ef + i);
    p[0] = __floats2half2_rn(v.x * SCALE_E, v.y * SCALE_E);
    p[1] = __floats2half2_rn(v.z * SCALE_E, v.w * SCALE_E);
}

// ---------------------------------------------------------------------------
// K1: split-K (2-way) partial of w0/w1. Block = (batch-group, j-half).
// Half 0 covers j in [0,256) -> operands from lhs; half 1 -> rel.
// Partials combined in k2. Bias folded into half 0.
// ---------------------------------------------------------------------------
#define K1_ROWS 4
__global__ __launch_bounds__(256) void k1_wproj(
    const int* __restrict__ x,
    const float* __restrict__ E_ent, const float* __restrict__ E_rel,
    const float* __restrict__ W0, const float* __restrict__ W1,
    const float* __restrict__ bw0, const float* __restrict__ bw1)
{
    const int bid = blockIdx.x;
    const int split = bid & 1;
    const int b0 = (bid >> 1) * K1_ROWS;
    const int tid = threadIdx.x;

    __shared__ float t0s[K1_ROWS][RANK];
    __shared__ float t1s[K1_ROWS][RANK];

    for (int rr = 0; rr < K1_ROWS; rr++) {
        const int b = b0 + rr;
        const size_t row_idx = (size_t)x[b * 3 + split];  // 0 -> lhs, 1 -> rel
        const float* row = (split == 0 ? E_ent : E_rel) + row_idx * TWO_R;
        t0s[rr][tid] = row[tid];
        t1s[rr][tid] = row[RANK + tid];
    }
    __syncthreads();

    const int k = tid;
    float a0[K1_ROWS], a1[K1_ROWS];
#pragma unroll
    for (int rr = 0; rr < K1_ROWS; rr++) { a0[rr] = 0.f; a1[rr] = 0.f; }

#pragma unroll 8
    for (int j = 0; j < RANK; j++) {
        const int jj = split * RANK + j;
        const float w0jk = W0[jj * RANK + k];
        const float w1jk = W1[jj * RANK + k];
#pragma unroll
        for (int rr = 0; rr < K1_ROWS; rr++) {
            const float a = t0s[rr][j];
            const float c = t1s[rr][j];
            a0[rr] += a * w0jk - c * w1jk;
            a1[rr] += a * w1jk + c * w0jk;
        }
    }
    const float b0k = split == 0 ? bw0[k] : 0.f;
    const float b1k = split == 0 ? bw1[k] : 0.f;
#pragma unroll
    for (int rr = 0; rr < K1_ROWS; rr++) {
        g_w0[split * BR + (b0 + rr) * RANK + k] = a0[rr] + b0k;
        g_w1[split * BR + (b0 + rr) * RANK + k] = a1[rr] + b1k;
    }
}

// ---------------------------------------------------------------------------
// K2: logits over 50 neighbors, softmax, ec0/ec1 weighted sums.
// Neighbor rows staged once into dynamic smem (100 KB) via cp.async.
// Combines the two k1 split-K partials while loading w.
// ---------------------------------------------------------------------------
#define K2_SMEM (MAX_NB * TWO_R * 4)   // 102400
__global__ __launch_bounds__(256) void k2_attn(
    const int* __restrict__ nb_idx, const float* __restrict__ E_ent)
{
    extern __shared__ __align__(16) float nbs[];   // [MAX_NB][TWO_R]
    __shared__ float w0s[RANK], w1s[RANK];
    __shared__ float logit_s[MAX_NB];
    __shared__ float alpha_s[MAX_NB];
    __shared__ int   idx_s[MAX_NB];

    const int b = blockIdx.x;
    const int tid = threadIdx.x;
    const int wid = tid >> 5;
    const int lane = tid & 31;

    w0s[tid] = g_w0[b * RANK + tid] + g_w0[BR + b * RANK + tid];
    w1s[tid] = g_w1[b * RANK + tid] + g_w1[BR + b * RANK + tid];
    if (tid < MAX_NB) idx_s[tid] = nb_idx[b * MAX_NB + tid];
    __syncthreads();

    const uint32_t nbs_u = smem_to_u32(nbs);
    for (int u = tid; u < MAX_NB * 128; u += 256) {
        const int m = u >> 7;
        const int q = u & 127;
        CP_ASYNC16(nbs_u + (uint32_t)u * 16,
                   E_ent + (size_t)idx_s[m] * TWO_R + q * 4);
    }
    CP_ASYNC_COMMIT();
    CP_ASYNC_WAIT_GROUP(0);
    __syncthreads();

    for (int m = wid; m < MAX_NB; m += 8) {
        const float* row = nbs + m * TWO_R;
        float s = 0.f;
#pragma unroll
        for (int k = lane; k < RANK; k += 32)
            s += w0s[k] * row[k] - w1s[k] * row[RANK + k];
#pragma unroll
        for (int o = 16; o > 0; o >>= 1) s += __shfl_xor_sync(0xffffffffu, s, o);
        if (lane == 0) logit_s[m] = s;
    }
    __syncthreads();

    if (tid == 0) {
        float mx = logit_s[0];
        for (int m = 1; m < MAX_NB; m++) mx = fmaxf(mx, logit_s[m]);
        float sum = 0.f;
        for (int m = 0; m < MAX_NB; m++) { float e = __expf(logit_s[m] - mx); alpha_s[m] = e; sum += e; }
        const float inv = 1.0f / sum;
        for (int m = 0; m < MAX_NB; m++) alpha_s[m] *= inv;
    }
    __syncthreads();

    const int k = tid;
    float acc0 = 0.f, acc1 = 0.f;
#pragma unroll 10
    for (int m = 0; m < MAX_NB; m++) {
        const float a = alpha_s[m];
        acc0 += a * nbs[m * TWO_R + k];
        acc1 += a * nbs[m * TWO_R + RANK + k];
    }
    g_ec0[b * RANK + k] = acc0;
    g_ec1[b * RANK + k] = acc1;
}

// ---------------------------------------------------------------------------
// K3a: split-K (4-way) partial of ec projection. Block = (batch-group, j-qtr).
// 1024 blocks of 64 j-iters each; partials combined in k3b. Bias in split 0.
// ---------------------------------------------------------------------------
#define K3_ROWS 4
#define K3_SPLIT 4
#define K3_J (RANK / K3_SPLIT)   // 64
__global__ __launch_bounds__(256) void k3a_ecproj(
    const float* __restrict__ W20, const float* __restrict__ W21,
    const float* __restrict__ bw20, const float* __restrict__ bw21)
{
    const int bid = blockIdx.x;
    const int split = bid & (K3_SPLIT - 1);
    const int b0 = (bid >> 2) * K3_ROWS;
    const int tid = threadIdx.x;

    __shared__ float e0s[K3_ROWS][K3_J];
    __shared__ float e1s[K3_ROWS][K3_J];

    {   // 256 threads load 4 rows x 64 cols in one pass
        const int rr = tid >> 6;
        const int j  = tid & 63;
        e0s[rr][j] = g_ec0[(b0 + rr) * RANK + split * K3_J + j];
        e1s[rr][j] = g_ec1[(b0 + rr) * RANK + split * K3_J + j];
    }
    __syncthreads();

    const int k = tid;
    float a0[K3_ROWS], a1[K3_ROWS];
#pragma unroll
    for (int rr = 0; rr < K3_ROWS; rr++) { a0[rr] = 0.f; a1[rr] = 0.f; }

#pragma unroll 8
    for (int j = 0; j < K3_J; j++) {
        const int jj = split * K3_J + j;
        const float w20 = W20[jj * RANK + k];
        const float w21 = W21[jj * RANK + k];
#pragma unroll
        for (int rr = 0; rr < K3_ROWS; rr++) {
            const float a = e0s[rr][j];
            const float c = e1s[rr][j];
            a0[rr] += a * w20 - c * w21;
            a1[rr] += a * w21 + c * w20;
        }
    }
    const float b20 = split == 0 ? bw20[k] : 0.f;
    const float b21 = split == 0 ? bw21[k] : 0.f;
#pragma unroll
    for (int rr = 0; rr < K3_ROWS; rr++) {
        g_en0[split * BR + (b0 + rr) * RANK + k] = a0[rr] + b20;
        g_en1[split * BR + (b0 + rr) * RANK + k] = a1[rr] + b21;
    }
}

// ---------------------------------------------------------------------------
// K3b: gate scalar, gec, q_re/q_im (scaled fp16 into g_Qf), norms.
// Combines the four k3a split-K partials while loading en.
// ---------------------------------------------------------------------------
__global__ __launch_bounds__(256) void k3b_gate_q(
    const int* __restrict__ x,
    const float* __restrict__ E_ent, const float* __restrict__ E_rel,
    const float* __restrict__ Uo0, const float* __restrict__ Uo1,
    const float* __restrict__ Wo0, const float* __restrict__ b_g,
    float* __restrict__ out)
{
    __shared__ float warp_part[8];
    __shared__ float g_sh2;
    const int b = blockIdx.x;
    const int k = threadIdx.x;
    const int wid = k >> 5, lane = k & 31;

    const size_t lhs = (size_t)x[b * 3 + 0];
    const size_t rel = (size_t)x[b * 3 + 1];
    const size_t rhs = (size_t)x[b * 3 + 2];

    const float l0 = E_ent[lhs * TWO_R + k];
    const float l1 = E_ent[lhs * TWO_R + RANK + k];
    const float r0 = E_rel[rel * TWO_R + k];
    const float r1 = E_rel[rel * TWO_R + RANK + k];
    const float o0 = E_ent[rhs * TWO_R + k];
    const float o1 = E_ent[rhs * TWO_R + RANK + k];

    const int ik = b * RANK + k;
    const float en0 = (g_en0[ik] + g_en0[BR + ik]) + (g_en0[2 * BR + ik] + g_en0[3 * BR + ik]);
    const float en1 = (g_en1[ik] + g_en1[BR + ik]) + (g_en1[2 * BR + ik] + g_en1[3 * BR + ik]);

    const float sr = l0 * r0 - l1 * r1;
    const float si = l1 * r0 + l0 * r1;

    float p = sr * Uo0[k] - si * Uo1[k] + en0 * Wo0[k];
#pragma unroll
    for (int o = 16; o > 0; o >>= 1) p += __shfl_xor_sync(0xffffffffu, p, o);
    if (lane == 0) warp_part[wid] = p;
    __syncthreads();
    if (k == 0) {
        float tot = 0.f;
#pragma unroll
        for (int w = 0; w < 8; w++) tot += warp_part[w];
        tot += b_g[0];
        g_sh2 = 1.0f / (1.0f + __expf(-tot));
    }
    __syncthreads();
    const float g = g_sh2;

    const float gec0 = g * en0 + (1.0f - g);
    const float gec1 = g * en1;

    const float q_re = sr * gec0 + si * gec1;
    const float q_im = si * gec0 - sr * gec1;

    g_Qf[b * TWO_R + k]        = __float2half_rn(q_re * SCALE_Q);
    g_Qf[b * TWO_R + RANK + k] = __float2half_rn(q_im * SCALE_Q);

    const size_t nk = (size_t)b * RANK + k;
    out[OFF_NLHS + nk] = sqrtf(l0 * l0 + l1 * l1);
    out[OFF_NREL + nk] = sqrtf(r0 * r0 + r1 * r1);
    out[OFF_NRHS + nk] = sqrtf(o0 * o0 + o1 * o1);
    out[OFF_NGEC + nk] = sqrtf(gec0 * gec0 + gec1 * gec1);
}

// ---------------------------------------------------------------------------
// K4: scores = Qf (1024x512) @ Ef^T (512x100000), single scaled-fp16 GEMM on
// mma.sync.m16n8k16. Persistent CTAs, continuous cp.async chunk stream,
// 3-stage pipeline, wait_group(1) (R8-proven configuration).
// ---------------------------------------------------------------------------
#define NCHUNK 8
#define NTILE_M (BATCH / 128)                 // 8
#define NTILE_N ((N_ENT + 255) / 256)         // 391
#define NTILES  (NTILE_M * NTILE_N)           // 3128
#define ROW_B    144                   // 128B data + 16B pad
#define A_TILE_B (128 * ROW_B)         // 18432
#define B_TILE_B (256 * ROW_B)         // 36864
#define STAGE_B  (A_TILE_B + B_TILE_B) // 55296
#define NSTAGE   3
#define SMEM_K4  (NSTAGE * STAGE_B)    // 165888
#define K4_THREADS 256

// Issue loads for global stream position p (tile = own-tile p>>3, chunk p&7)
__device__ __forceinline__ void k4_load_pos(
    uint32_t sbase, int p, int stg, int bidx, int gridx,
    const __half* Qf, const __half* Ef, int tid)
{
    const int T = bidx + (p >> 3) * gridx;
    const int chunk = p & 7;
    const int m0 = (T & (NTILE_M - 1)) * 128;
    const int n0 = (T / NTILE_M) * 256;
    const int k0 = chunk * 64;
    const uint32_t sb = sbase + (uint32_t)stg * STAGE_B;
    // A tile: 128 rows x 8 x 16B = 1024 transfers
#pragma unroll
    for (int u = 0; u < 4; u++) {
        const int idx = tid + u * K4_THREADS;   // 0..1023
        const int row = idx >> 3;
        const int g   = idx & 7;
        const uint32_t soff = sb + (uint32_t)(row * ROW_B + g * 16);
        CP_ASYNC16(soff, Qf + (size_t)(m0 + row) * TWO_R + k0 + g * 8);
    }
    // B tile: 256 rows x 8 x 16B = 2048 transfers
#pragma unroll
    for (int u = 0; u < 8; u++) {
        const int idx = tid + u * K4_THREADS;   // 0..2047
        const int row = idx >> 3;
        const int g   = idx & 7;
        int er = n0 + row; if (er >= N_ENT) er = N_ENT - 1;
        const uint32_t soff = sb + (uint32_t)(A_TILE_B + row * ROW_B + g * 16);
        CP_ASYNC16(soff, Ef + (size_t)er * TWO_R + k0 + g * 8);
    }
}

__global__ __launch_bounds__(K4_THREADS, 1) void k4_hmma(
    const __half* __restrict__ Qf, const __half* __restrict__ Ef,
    float* __restrict__ C)
{
    extern __shared__ __align__(1024) char smem[];
    const uint32_t sbase = smem_to_u32(smem);
    const int tid  = threadIdx.x;
    const int wid  = tid >> 5;
    const int lane = tid & 31;
    const int wm   = wid & 1;       // 0..1 -> 64-row slice
    const int wn   = wid >> 1;      // 0..3 -> 64-col slice
    const int bidx = blockIdx.x;
    const int gridx = gridDim.x;

    const int ntiles_own = (NTILES - bidx + gridx - 1) / gridx;
    const int pmax = ntiles_own * NCHUNK;

    const int laneRow = ((lane >> 3) & 1) * 8 + (lane & 7);
    const int laneG   = lane >> 4;
    const int rowAbase = wm * 64 + laneRow;
    const int rowBbase = wn * 64 + laneRow;

    // preload stream positions 0 and 1
    k4_load_pos(sbase, 0, 0, bidx, gridx, Qf, Ef, tid);
    CP_ASYNC_COMMIT();
    if (pmax > 1) k4_load_pos(sbase, 1, 1, bidx, gridx, Qf, Ef, tid);
    CP_ASYNC_COMMIT();

    int p_load = 2;
    int stg_load = 2;
    int stg = 0;

#pragma unroll 1
    for (int j = 0; j < ntiles_own; j++) {
        const int T = bidx + j * gridx;
        const int m0 = (T & (NTILE_M - 1)) * 128;
        const int n0 = (T / NTILE_M) * 256;

        float acc[4][8][4];
#pragma unroll
        for (int a = 0; a < 4; a++)
#pragma unroll
            for (int b = 0; b < 8; b++)
#pragma unroll
                for (int c = 0; c < 4; c++) acc[a][b][c] = 0.f;

#pragma unroll 1
        for (int i = 0; i < NCHUNK; i++) {
            CP_ASYNC_WAIT_GROUP(1);
            __syncthreads();

            if (p_load < pmax)
                k4_load_pos(sbase, p_load, stg_load, bidx, gridx, Qf, Ef, tid);
            CP_ASYNC_COMMIT();
            p_load++;
            stg_load = stg_load + 1; if (stg_load >= NSTAGE) stg_load = 0;

            const uint32_t sA = sbase + (uint32_t)stg * STAGE_B;
            const uint32_t sB = sA + A_TILE_B;

#pragma unroll
            for (int kh = 0; kh < 4; kh++) {
                const uint32_t gof = (uint32_t)(kh * 32 + laneG * 16);

                uint32_t a_op[4][4], b_op[4][4];
#pragma unroll
                for (int mt = 0; mt < 4; mt++)
                    ldsm_x4(a_op[mt], sA + (uint32_t)((rowAbase + mt * 16) * ROW_B) + gof);
#pragma unroll
                for (int q = 0; q < 4; q++)
                    ldsm_x4(b_op[q], sB + (uint32_t)((rowBbase + q * 16) * ROW_B) + gof);

#pragma unroll
                for (int mt = 0; mt < 4; mt++)
#pragma unroll
                    for (int jj = 0; jj < 8; jj++)
                        mma_16816_f16(acc[mt][jj], a_op[mt],
                                      b_op[jj >> 1][jj & 1], b_op[jj >> 1][2 + (jj & 1)]);
            }

            stg = stg + 1; if (stg >= NSTAGE) stg = 0;
        }

        // Epilogue (overlaps with next tile's in-flight cp.async loads)
        const int erow = (lane >> 2);
        const int ecol = (lane & 3) * 2;
#pragma unroll
        for (int mt = 0; mt < 4; mt++) {
            const int r1 = m0 + wm * 64 + mt * 16 + erow;
#pragma unroll
            for (int jj = 0; jj < 8; jj++) {
                const int n = n0 + wn * 64 + jj * 8 + ecol;
                if (n < N_ENT) {
                    float2 v01 = make_float2(acc[mt][jj][0] * SCALE_OUT,
                                             acc[mt][jj][1] * SCALE_OUT);
                    float2 v23 = make_float2(acc[mt][jj][2] * SCALE_OUT,
                                             acc[mt][jj][3] * SCALE_OUT);
                    *(float2*)(C + (size_t)r1 * N_ENT + n) = v01;
                    *(float2*)(C + (size_t)(r1 + 8) * N_ENT + n) = v23;
                }
            }
        }
    }
}

// ---------------------------------------------------------------------------
extern "C" void kernel_launch(void* const* d_in, const int* in_sizes, int n_in,
                              void* d_out, int out_size)
{
    const int*   x      = (const int*)  d_in[0];
    const int*   nb_idx = (const int*)  d_in[1];
    const float* E_ent  = (const float*)d_in[2];
    const float* E_rel  = (const float*)d_in[3];
    const float* W0     = (const float*)d_in[4];
    const float* W1     = (const float*)d_in[5];
    const float* bw0    = (const float*)d_in[6];
    const float* bw1    = (const float*)d_in[7];
    const float* W20    = (const float*)d_in[8];
    const float* W21    = (const float*)d_in[9];
    const float* bw20   = (const float*)d_in[10];
    const float* bw21   = (const float*)d_in[11];
    const float* Uo0    = (const float*)d_in[12];
    const float* Uo1    = (const float*)d_in[13];
    const float* Wo0    = (const float*)d_in[14];
    const float* b_g    = (const float*)d_in[15];
    float* out = (float*)d_out;

    __half *Qf, *Ef;
    cudaGetSymbolAddress((void**)&Qf, g_Qf);
    cudaGetSymbolAddress((void**)&Ef, g_Ef);

    cudaFuncSetAttribute(k4_hmma, cudaFuncAttributeMaxDynamicSharedMemorySize, SMEM_K4);
    cudaFuncSetAttribute(k2_attn, cudaFuncAttributeMaxDynamicSharedMemorySize, K2_SMEM);

    int nsm = 148;
    cudaDeviceGetAttribute(&nsm, cudaDevAttrMultiProcessorCount, 0);

    k0_cvtE<<<50000, 256>>>(E_ent);

    k1_wproj  <<<(BATCH / K1_ROWS) * 2, 256>>>(x, E_ent, E_rel, W0, W1, bw0, bw1);
    k2_attn   <<<BATCH, 256, K2_SMEM>>>(nb_idx, E_ent);
    k3a_ecproj<<<(BATCH / K3_ROWS) * K3_SPLIT, 256>>>(W20, W21, bw20, bw21);
    k3b_gate_q<<<BATCH, 256>>>(x, E_ent, E_rel, Uo0, Uo1, Wo0, b_g, out);

    k4_hmma<<<nsm, K4_THREADS, SMEM_K4>>>(Qf, Ef, out + OFF_SCORES);
}

// round 13
// speedup vs baseline: 1.1336x; 1.0078x over previous
#include <cuda_runtime.h>
#include <cuda_bf16.h>
#include <cuda_fp16.h>
#include <cstdint>
#include <math.h>

// Problem constants
#define N_ENT 100000
#define N_REL 1000
#define RANK  256
#define TWO_R 512
#define BATCH 1024
#define MAX_NB 50

// Output layout (flattened tuple): scores, n_lhs, n_rel, n_rhs, n_gec
#define OFF_SCORES 0
#define OFF_NLHS   ((size_t)BATCH * N_ENT)
#define OFF_NREL   (OFF_NLHS + (size_t)BATCH * RANK)
#define OFF_NRHS   (OFF_NREL + (size_t)BATCH * RANK)
#define OFF_NGEC   (OFF_NRHS + (size_t)BATCH * RANK)

// Power-of-2 scaling for fp16 GEMM (exact, no extra rounding)
#define SCALE_Q 1048576.0f            // 2^20
#define SCALE_E 1024.0f               // 2^10
#define SCALE_OUT 9.313225746154785e-10f   // 2^-30

#define BR (BATCH * RANK)

// Scratch (static device globals; no allocation allowed)
// w and en are SPLIT-K partial buffers (combined by the consumer kernels)
#define K1_SPLIT 4
#define K3_SPLIT 8
__device__ float g_w0 [K1_SPLIT * BR];
__device__ float g_w1 [K1_SPLIT * BR];
__device__ float g_ec0[BR];
__device__ float g_ec1[BR];
__device__ float g_en0[K3_SPLIT * BR];
__device__ float g_en1[K3_SPLIT * BR];

// scaled fp16 operands for the big GEMM
__device__ __half g_Qf[BATCH * TWO_R];
__device__ __half g_Ef[(size_t)N_ENT * TWO_R];

// ===========================================================================
// PTX helpers (compute_103-safe subset: cp.async / ldmatrix / mma.sync only)
// ===========================================================================
__device__ __forceinline__ uint32_t smem_to_u32(const void* smem_ptr) {
    uint32_t addr;
    asm("{ .reg .u64 tmp; cvta.to.shared.u64 tmp, %1; cvt.u32.u64 %0, tmp; }"
        : "=r"(addr) : "l"(smem_ptr));
    return addr;
}

#define CP_ASYNC16(smem_u32, gptr) \
    asm volatile("cp.async.cg.shared.global [%0], [%1], 16;" \
        :: "r"(smem_u32), "l"(gptr) : "memory")

#define CP_ASYNC_COMMIT() \
    asm volatile("cp.async.commit_group;" ::: "memory")

#define CP_ASYNC_WAIT_GROUP(n) \
    asm volatile("cp.async.wait_group %0;" :: "n"(n) : "memory")

__device__ __forceinline__ void ldsm_x4(uint32_t r[4], uint32_t addr) {
    asm volatile("ldmatrix.sync.aligned.m8n8.x4.shared.b16 {%0,%1,%2,%3}, [%4];"
        : "=r"(r[0]), "=r"(r[1]), "=r"(r[2]), "=r"(r[3]) : "r"(addr));
}

__device__ __forceinline__ void mma_16816_f16(
    float c[4], const uint32_t a[4], uint32_t b0, uint32_t b1)
{
    asm volatile(
        "mma.sync.aligned.m16n8k16.row.col.f32.f16.f16.f32 "
        "{%0,%1,%2,%3}, {%4,%5,%6,%7}, {%8,%9}, {%0,%1,%2,%3};"
        : "+f"(c[0]), "+f"(c[1]), "+f"(c[2]), "+f"(c[3])
        : "r"(a[0]), "r"(a[1]), "r"(a[2]), "r"(a[3]), "r"(b0), "r"(b1));
}

// ---------------------------------------------------------------------------
// K0: convert E_ent (fp32) into scaled fp16
// ---------------------------------------------------------------------------
__global__ __launch_bounds__(256) void k0_cvtE(const float* __restrict__ E)
{
    const size_t i = ((size_t)blockIdx.x * 256 + threadIdx.x) * 4;
    const float4 v = *(const float4*)(E + i);
    __half2* p = (__half2*)(g_Ef + i);
    p[0] = __floats2half2_rn(v.x * SCALE_E, v.y * SCALE_E);
    p[1] = __floats2half2_rn(v.z * SCALE_E, v.w * SCALE_E);
}

// ---------------------------------------------------------------------------
// K1: split-K (4-way) partial of w0/w1. Block = (batch-group, j-quarter).
// Splits 0,1 cover j in [0,256) -> operands from lhs; 2,3 -> rel.
// Partials combined in k2. Bias folded into split 0.
// ---------------------------------------------------------------------------
#define K1_ROWS 4
#define K1_J (TWO_R / K1_SPLIT)   // 128
__global__ __launch_bounds__(256) void k1_wproj(
    const int* __restrict__ x,
    const float* __restrict__ E_ent, const float* __restrict__ E_rel,
    const float* __restrict__ W0, const float* __restrict__ W1,
    const float* __restrict__ bw0, const float* __restrict__ bw1)
{
    const int bid = blockIdx.x;
    const int split = bid & (K1_SPLIT - 1);
    const int b0 = (bid >> 2) * K1_ROWS;
    const int tid = threadIdx.x;

    __shared__ float t0s[K1_ROWS][K1_J];
    __shared__ float t1s[K1_ROWS][K1_J];

    const int src = split >> 1;          // 0 -> lhs (E_ent), 1 -> rel (E_rel)
    const int off = (split & 1) * K1_J;  // 0 or 128 within the rank half
    for (int rr = 0; rr < K1_ROWS; rr++) {
        const int b = b0 + rr;
        const size_t row_idx = (size_t)x[b * 3 + src];
        const float* row = (src == 0 ? E_ent : E_rel) + row_idx * TWO_R;
        if (tid < K1_J) t0s[rr][tid] = row[off + tid];
        else            t1s[rr][tid - K1_J] = row[RANK + off + (tid - K1_J)];
    }
    __syncthreads();

    const int k = tid;
    float a0[K1_ROWS], a1[K1_ROWS];
#pragma unroll
    for (int rr = 0; rr < K1_ROWS; rr++) { a0[rr] = 0.f; a1[rr] = 0.f; }

#pragma unroll 8
    for (int j = 0; j < K1_J; j++) {
        const int jj = split * K1_J + j;
        const float w0jk = W0[jj * RANK + k];
        const float w1jk = W1[jj * RANK + k];
#pragma unroll
        for (int rr = 0; rr < K1_ROWS; rr++) {
            const float a = t0s[rr][j];
            const float c = t1s[rr][j];
            a0[rr] += a * w0jk - c * w1jk;
            a1[rr] += a * w1jk + c * w0jk;
        }
    }
    const float b0k = split == 0 ? bw0[k] : 0.f;
    const float b1k = split == 0 ? bw1[k] : 0.f;
#pragma unroll
    for (int rr = 0; rr < K1_ROWS; rr++) {
        g_w0[split * BR + (b0 + rr) * RANK + k] = a0[rr] + b0k;
        g_w1[split * BR + (b0 + rr) * RANK + k] = a1[rr] + b1k;
    }
}

// ---------------------------------------------------------------------------
// K2: logits over 50 neighbors, softmax, ec0/ec1 weighted sums.
// Neighbor rows staged once into dynamic smem (100 KB) via cp.async.
// Combines the four k1 split-K partials while loading w.
// ---------------------------------------------------------------------------
#define K2_SMEM (MAX_NB * TWO_R * 4)   // 102400
__global__ __launch_bounds__(256) void k2_attn(
    const int* __restrict__ nb_idx, const float* __restrict__ E_ent)
{
    extern __shared__ __align__(16) float nbs[];   // [MAX_NB][TWO_R]
    __shared__ float w0s[RANK], w1s[RANK];
    __shared__ float logit_s[MAX_NB];
    __shared__ float alpha_s[MAX_NB];
    __shared__ int   idx_s[MAX_NB];

    const int b = blockIdx.x;
    const int tid = threadIdx.x;
    const int wid = tid >> 5;
    const int lane = tid & 31;

    {
        const int ik = b * RANK + tid;
        w0s[tid] = (g_w0[ik] + g_w0[BR + ik]) + (g_w0[2 * BR + ik] + g_w0[3 * BR + ik]);
        w1s[tid] = (g_w1[ik] + g_w1[BR + ik]) + (g_w1[2 * BR + ik] + g_w1[3 * BR + ik]);
    }
    if (tid < MAX_NB) idx_s[tid] = nb_idx[b * MAX_NB + tid];
    __syncthreads();

    const uint32_t nbs_u = smem_to_u32(nbs);
    for (int u = tid; u < MAX_NB * 128; u += 256) {
        const int m = u >> 7;
        const int q = u & 127;
        CP_ASYNC16(nbs_u + (uint32_t)u * 16,
                   E_ent + (size_t)idx_s[m] * TWO_R + q * 4);
    }
    CP_ASYNC_COMMIT();
    CP_ASYNC_WAIT_GROUP(0);
    __syncthreads();

    for (int m = wid; m < MAX_NB; m += 8) {
        const float* row = nbs + m * TWO_R;
        float s = 0.f;
#pragma unroll
        for (int k = lane; k < RANK; k += 32)
            s += w0s[k] * row[k] - w1s[k] * row[RANK + k];
#pragma unroll
        for (int o = 16; o > 0; o >>= 1) s += __shfl_xor_sync(0xffffffffu, s, o);
        if (lane == 0) logit_s[m] = s;
    }
    __syncthreads();

    if (tid == 0) {
        float mx = logit_s[0];
        for (int m = 1; m < MAX_NB; m++) mx = fmaxf(mx, logit_s[m]);
        float sum = 0.f;
        for (int m = 0; m < MAX_NB; m++) { float e = __expf(logit_s[m] - mx); alpha_s[m] = e; sum += e; }
        const float inv = 1.0f / sum;
        for (int m = 0; m < MAX_NB; m++) alpha_s[m] *= inv;
    }
    __syncthreads();

    const int k = tid;
    float acc0 = 0.f, acc1 = 0.f;
#pragma unroll 10
    for (int m = 0; m < MAX_NB; m++) {
        const float a = alpha_s[m];
        acc0 += a * nbs[m * TWO_R + k];
        acc1 += a * nbs[m * TWO_R + RANK + k];
    }
    g_ec0[b * RANK + k] = acc0;
    g_ec1[b * RANK + k] = acc1;
}

// ---------------------------------------------------------------------------
// K3a: split-K (8-way) partial of ec projection. Block = (batch-group, j-8th).
// 2048 blocks of 32 j-iters each; partials combined in k3b. Bias in split 0.
// ---------------------------------------------------------------------------
#define K3_ROWS 4
#define K3_J (RANK / K3_SPLIT)   // 32
__global__ __launch_bounds__(256) void k3a_ecproj(
    const float* __restrict__ W20, const float* __restrict__ W21,
    const float* __restrict__ bw20, const float* __restrict__ bw21)
{
    const int bid = blockIdx.x;
    const int split = bid & (K3_SPLIT - 1);
    const int b0 = (bid >> 3) * K3_ROWS;
    const int tid = threadIdx.x;

    __shared__ float e0s[K3_ROWS][K3_J];
    __shared__ float e1s[K3_ROWS][K3_J];

    {   // 256 threads load 2 arrays x 4 rows x 32 cols in one pass
        const int arr = tid >> 7;          // 0 -> e0, 1 -> e1
        const int rem = tid & 127;
        const int rr  = rem >> 5;
        const int j   = rem & 31;
        const float v = (arr == 0 ? g_ec0 : g_ec1)[(b0 + rr) * RANK + split * K3_J + j];
        if (arr == 0) e0s[rr][j] = v; else e1s[rr][j] = v;
    }
    __syncthreads();

    const int k = tid;
    float a0[K3_ROWS], a1[K3_ROWS];
#pragma unroll
    for (int rr = 0; rr < K3_ROWS; rr++) { a0[rr] = 0.f; a1[rr] = 0.f; }

#pragma unroll 8
    for (int j = 0; j < K3_J; j++) {
        const int jj = split * K3_J + j;
        const float w20 = W20[jj * RANK + k];
        const float w21 = W21[jj * RANK + k];
#pragma unroll
        for (int rr = 0; rr < K3_ROWS; rr++) {
            const float a = e0s[rr][j];
            const float c = e1s[rr][j];
            a0[rr] += a * w20 - c * w21;
            a1[rr] += a * w21 + c * w20;
        }
    }
    const float b20 = split == 0 ? bw20[k] : 0.f;
    const float b21 = split == 0 ? bw21[k] : 0.f;
#pragma unroll
    for (int rr = 0; rr < K3_ROWS; rr++) {
        g_en0[split * BR + (b0 + rr) * RANK + k] = a0[rr] + b20;
        g_en1[split * BR + (b0 + rr) * RANK + k] = a1[rr] + b21;
    }
}

// ---------------------------------------------------------------------------
// K3b: gate scalar, gec, q_re/q_im (scaled fp16 into g_Qf), norms.
// Combines the eight k3a split-K partials while loading en.
// ---------------------------------------------------------------------------
__global__ __launch_bounds__(256) void k3b_gate_q(
    const int* __restrict__ x,
    const float* __restrict__ E_ent, const float* __restrict__ E_rel,
    const float* __restrict__ Uo0, const float* __restrict__ Uo1,
    const float* __restrict__ Wo0, const float* __restrict__ b_g,
    float* __restrict__ out)
{
    __shared__ float warp_part[8];
    __shared__ float g_sh2;
    const int b = blockIdx.x;
    const int k = threadIdx.x;
    const int wid = k >> 5, lane = k & 31;

    const size_t lhs = (size_t)x[b * 3 + 0];
    const size_t rel = (size_t)x[b * 3 + 1];
    const size_t rhs = (size_t)x[b * 3 + 2];

    const float l0 = E_ent[lhs * TWO_R + k];
    const float l1 = E_ent[lhs * TWO_R + RANK + k];
    const float r0 = E_rel[rel * TWO_R + k];
    const float r1 = E_rel[rel * TWO_R + RANK + k];
    const float o0 = E_ent[rhs * TWO_R + k];
    const float o1 = E_ent[rhs * TWO_R + RANK + k];

    const int ik = b * RANK + k;
    float en0 = 0.f, en1 = 0.f;
#pragma unroll
    for (int s = 0; s < K3_SPLIT; s++) {
        en0 += g_en0[s * BR + ik];
        en1 += g_en1[s * BR + ik];
    }

    const float sr = l0 * r0 - l1 * r1;
    const float si = l1 * r0 + l0 * r1;

    float p = sr * Uo0[k] - si * Uo1[k] + en0 * Wo0[k];
#pragma unroll
    for (int o = 16; o > 0; o >>= 1) p += __shfl_xor_sync(0xffffffffu, p, o);
    if (lane == 0) warp_part[wid] = p;
    __syncthreads();
    if (k == 0) {
        float tot = 0.f;
#pragma unroll
        for (int w = 0; w < 8; w++) tot += warp_part[w];
        tot += b_g[0];
        g_sh2 = 1.0f / (1.0f + __expf(-tot));
    }
    __syncthreads();
    const float g = g_sh2;

    const float gec0 = g * en0 + (1.0f - g);
    const float gec1 = g * en1;

    const float q_re = sr * gec0 + si * gec1;
    const float q_im = si * gec0 - sr * gec1;

    g_Qf[b * TWO_R + k]        = __float2half_rn(q_re * SCALE_Q);
    g_Qf[b * TWO_R + RANK + k] = __float2half_rn(q_im * SCALE_Q);

    const size_t nk = (size_t)b * RANK + k;
    out[OFF_NLHS + nk] = sqrtf(l0 * l0 + l1 * l1);
    out[OFF_NREL + nk] = sqrtf(r0 * r0 + r1 * r1);
    out[OFF_NRHS + nk] = sqrtf(o0 * o0 + o1 * o1);
    out[OFF_NGEC + nk] = sqrtf(gec0 * gec0 + gec1 * gec1);
}

// ---------------------------------------------------------------------------
// K4: scores = Qf (1024x512) @ Ef^T (512x100000), single scaled-fp16 GEMM on
// mma.sync.m16n8k16. Persistent CTAs, continuous cp.async chunk stream,
// 3-stage pipeline, wait_group(1) (R8-proven configuration).
// ---------------------------------------------------------------------------
#define NCHUNK 8
#define NTILE_M (BATCH / 128)                 // 8
#define NTILE_N ((N_ENT + 255) / 256)         // 391
#define NTILES  (NTILE_M * NTILE_N)           // 3128
#define ROW_B    144                   // 128B data + 16B pad
#define A_TILE_B (128 * ROW_B)         // 18432
#define B_TILE_B (256 * ROW_B)         // 36864
#define STAGE_B  (A_TILE_B + B_TILE_B) // 55296
#define NSTAGE   3
#define SMEM_K4  (NSTAGE * STAGE_B)    // 165888
#define K4_THREADS 256

// Issue loads for global stream position p (tile = own-tile p>>3, chunk p&7)
__device__ __forceinline__ void k4_load_pos(
    uint32_t sbase, int p, int stg, int bidx, int gridx,
    const __half* Qf, const __half* Ef, int tid)
{
    const int T = bidx + (p >> 3) * gridx;
    const int chunk = p & 7;
    const int m0 = (T & (NTILE_M - 1)) * 128;
    const int n0 = (T / NTILE_M) * 256;
    const int k0 = chunk * 64;
    const uint32_t sb = sbase + (uint32_t)stg * STAGE_B;
    // A tile: 128 rows x 8 x 16B = 1024 transfers
#pragma unroll
    for (int u = 0; u < 4; u++) {
        const int idx = tid + u * K4_THREADS;   // 0..1023
        const int row = idx >> 3;
        const int g   = idx & 7;
        const uint32_t soff = sb + (uint32_t)(row * ROW_B + g * 16);
        CP_ASYNC16(soff, Qf + (size_t)(m0 + row) * TWO_R + k0 + g * 8);
    }
    // B tile: 256 rows x 8 x 16B = 2048 transfers
#pragma unroll
    for (int u = 0; u < 8; u++) {
        const int idx = tid + u * K4_THREADS;   // 0..2047
        const int row = idx >> 3;
        const int g   = idx & 7;
        int er = n0 + row; if (er >= N_ENT) er = N_ENT - 1;
        const uint32_t soff = sb + (uint32_t)(A_TILE_B + row * ROW_B + g * 16);
        CP_ASYNC16(soff, Ef + (size_t)er * TWO_R + k0 + g * 8);
    }
}

__global__ __launch_bounds__(K4_THREADS, 1) void k4_hmma(
    const __half* __restrict__ Qf, const __half* __restrict__ Ef,
    float* __restrict__ C)
{
    extern __shared__ __align__(1024) char smem[];
    const uint32_t sbase = smem_to_u32(smem);
    const int tid  = threadIdx.x;
    const int wid  = tid >> 5;
    const int lane = tid & 31;
    const int wm   = wid & 1;       // 0..1 -> 64-row slice
    const int wn   = wid >> 1;      // 0..3 -> 64-col slice
    const int bidx = blockIdx.x;
    const int gridx = gridDim.x;

    const int ntiles_own = (NTILES - bidx + gridx - 1) / gridx;
    const int pmax = ntiles_own * NCHUNK;

    const int laneRow = ((lane >> 3) & 1) * 8 + (lane & 7);
    const int laneG   = lane >> 4;
    const int rowAbase = wm * 64 + laneRow;
    const int rowBbase = wn * 64 + laneRow;

    // preload stream positions 0 and 1
    k4_load_pos(sbase, 0, 0, bidx, gridx, Qf, Ef, tid);
    CP_ASYNC_COMMIT();
    if (pmax > 1) k4_load_pos(sbase, 1, 1, bidx, gridx, Qf, Ef, tid);
    CP_ASYNC_COMMIT();

    int p_load = 2;
    int stg_load = 2;
    int stg = 0;

#pragma unroll 1
    for (int j = 0; j < ntiles_own; j++) {
        const int T = bidx + j * gridx;
        const int m0 = (T & (NTILE_M - 1)) * 128;
        const int n0 = (T / NTILE_M) * 256;

        float acc[4][8][4];
#pragma unroll
        for (int a = 0; a < 4; a++)
#pragma unroll
            for (int b = 0; b < 8; b++)
#pragma unroll
                for (int c = 0; c < 4; c++) acc[a][b][c] = 0.f;

#pragma unroll 1
        for (int i = 0; i < NCHUNK; i++) {
            CP_ASYNC_WAIT_GROUP(1);
            __syncthreads();

            if (p_load < pmax)
                k4_load_pos(sbase, p_load, stg_load, bidx, gridx, Qf, Ef, tid);
            CP_ASYNC_COMMIT();
            p_load++;
            stg_load = stg_load + 1; if (stg_load >= NSTAGE) stg_load = 0;

            const uint32_t sA = sbase + (uint32_t)stg * STAGE_B;
            const uint32_t sB = sA + A_TILE_B;

#pragma unroll
            for (int kh = 0; kh < 4; kh++) {
                const uint32_t gof = (uint32_t)(kh * 32 + laneG * 16);

                uint32_t a_op[4][4], b_op[4][4];
#pragma unroll
                for (int mt = 0; mt < 4; mt++)
                    ldsm_x4(a_op[mt], sA + (uint32_t)((rowAbase + mt * 16) * ROW_B) + gof);
#pragma unroll
                for (int q = 0; q < 4; q++)
                    ldsm_x4(b_op[q], sB + (uint32_t)((rowBbase + q * 16) * ROW_B) + gof);

#pragma unroll
                for (int mt = 0; mt < 4; mt++)
#pragma unroll
                    for (int jj = 0; jj < 8; jj++)
                        mma_16816_f16(acc[mt][jj], a_op[mt],
                                      b_op[jj >> 1][jj & 1], b_op[jj >> 1][2 + (jj & 1)]);
            }

            stg = stg + 1; if (stg >= NSTAGE) stg = 0;
        }

        // Epilogue (overlaps with next tile's in-flight cp.async loads)
        const int erow = (lane >> 2);
        const int ecol = (lane & 3) * 2;
#pragma unroll
        for (int mt = 0; mt < 4; mt++) {
            const int r1 = m0 + wm * 64 + mt * 16 + erow;
#pragma unroll
            for (int jj = 0; jj < 8; jj++) {
                const int n = n0 + wn * 64 + jj * 8 + ecol;
                if (n < N_ENT) {
                    float2 v01 = make_float2(acc[mt][jj][0] * SCALE_OUT,
                                             acc[mt][jj][1] * SCALE_OUT);
                    float2 v23 = make_float2(acc[mt][jj][2] * SCALE_OUT,
                                             acc[mt][jj][3] * SCALE_OUT);
                    *(float2*)(C + (size_t)r1 * N_ENT + n) = v01;
                    *(float2*)(C + (size_t)(r1 + 8) * N_ENT + n) = v23;
                }
            }
        }
    }
}

// ---------------------------------------------------------------------------
extern "C" void kernel_launch(void* const* d_in, const int* in_sizes, int n_in,
                              void* d_out, int out_size)
{
    const int*   x      = (const int*)  d_in[0];
    const int*   nb_idx = (const int*)  d_in[1];
    const float* E_ent  = (const float*)d_in[2];
    const float* E_rel  = (const float*)d_in[3];
    const float* W0     = (const float*)d_in[4];
    const float* W1     = (const float*)d_in[5];
    const float* bw0    = (const float*)d_in[6];
    const float* bw1    = (const float*)d_in[7];
    const float* W20    = (const float*)d_in[8];
    const float* W21    = (const float*)d_in[9];
    const float* bw20   = (const float*)d_in[10];
    const float* bw21   = (const float*)d_in[11];
    const float* Uo0    = (const float*)d_in[12];
    const float* Uo1    = (const float*)d_in[13];
    const float* Wo0    = (const float*)d_in[14];
    const float* b_g    = (const float*)d_in[15];
    float* out = (float*)d_out;

    __half *Qf, *Ef;
    cudaGetSymbolAddress((void**)&Qf, g_Qf);
    cudaGetSymbolAddress((void**)&Ef, g_Ef);

    cudaFuncSetAttribute(k4_hmma, cudaFuncAttributeMaxDynamicSharedMemorySize, SMEM_K4);
    cudaFuncSetAttribute(k2_attn, cudaFuncAttributeMaxDynamicSharedMemorySize, K2_SMEM);

    int nsm = 148;
    cudaDeviceGetAttribute(&nsm, cudaDevAttrMultiProcessorCount, 0);

    k0_cvtE<<<50000, 256>>>(E_ent);

    k1_wproj  <<<(BATCH / K1_ROWS) * K1_SPLIT, 256>>>(x, E_ent, E_rel, W0, W1, bw0, bw1);
    k2_attn   <<<BATCH, 256, K2_SMEM>>>(nb_idx, E_ent);
    k3a_ecproj<<<(BATCH / K3_ROWS) * K3_SPLIT, 256>>>(W20, W21, bw20, bw21);
    k3b_gate_q<<<BATCH, 256>>>(x, E_ent, E_rel, Uo0, Uo1, Wo0, b_g, out);

    k4_hmma<<<nsm, K4_THREADS, SMEM_K4>>>(Qf, Ef, out + OFF_SCORES);
}

// round 15
// speedup vs baseline: 1.1431x; 1.0083x over previous
#include <cuda_runtime.h>
#include <cuda_bf16.h>
#include <cuda_fp16.h>
#include <cstdint>
#include <math.h>

// Problem constants
#define N_ENT 100000
#define N_REL 1000
#define RANK  256
#define TWO_R 512
#define BATCH 1024
#define MAX_NB 50

// Output layout (flattened tuple): scores, n_lhs, n_rel, n_rhs, n_gec
#define OFF_SCORES 0
#define OFF_NLHS   ((size_t)BATCH * N_ENT)
#define OFF_NREL   (OFF_NLHS + (size_t)BATCH * RANK)
#define OFF_NRHS   (OFF_NREL + (size_t)BATCH * RANK)
#define OFF_NGEC   (OFF_NRHS + (size_t)BATCH * RANK)

// Power-of-2 scaling for fp16 GEMM (exact, no extra rounding)
#define SCALE_Q 1048576.0f            // 2^20
#define SCALE_E 1024.0f               // 2^10
#define SCALE_OUT 9.313225746154785e-10f   // 2^-30

#define BR (BATCH * RANK)

// Scratch (static device globals; no allocation allowed)
#define K1_SPLIT 4
#define K3_SPLIT 8
__device__ float g_w0 [K1_SPLIT * BR];
__device__ float g_w1 [K1_SPLIT * BR];
__device__ float g_ec0[BR];
__device__ float g_ec1[BR];
__device__ float g_en0[K3_SPLIT * BR];
__device__ float g_en1[K3_SPLIT * BR];

// scaled fp16 operands for the big GEMM
__device__ __half g_Qf[BATCH * TWO_R];
__device__ __half g_Ef[(size_t)N_ENT * TWO_R];

// ===========================================================================
// PTX helpers (compute_103-safe subset: cp.async / ldmatrix / mma.sync only)
// ===========================================================================
__device__ __forceinline__ uint32_t smem_to_u32(const void* smem_ptr) {
    uint32_t addr;
    asm("{ .reg .u64 tmp; cvta.to.shared.u64 tmp, %1; cvt.u32.u64 %0, tmp; }"
        : "=r"(addr) : "l"(smem_ptr));
    return addr;
}

#define CP_ASYNC16(smem_u32, gptr) \
    asm volatile("cp.async.cg.shared.global [%0], [%1], 16;" \
        :: "r"(smem_u32), "l"(gptr) : "memory")

#define CP_ASYNC_COMMIT() \
    asm volatile("cp.async.commit_group;" ::: "memory")

#define CP_ASYNC_WAIT_GROUP(n) \
    asm volatile("cp.async.wait_group %0;" :: "n"(n) : "memory")

__device__ __forceinline__ void ldsm_x4(uint32_t r[4], uint32_t addr) {
    asm volatile("ldmatrix.sync.aligned.m8n8.x4.shared.b16 {%0,%1,%2,%3}, [%4];"
        : "=r"(r[0]), "=r"(r[1]), "=r"(r[2]), "=r"(r[3]) : "r"(addr));
}

__device__ __forceinline__ void mma_16816_f16(
    float c[4], const uint32_t a[4], uint32_t b0, uint32_t b1)
{
    asm volatile(
        "mma.sync.aligned.m16n8k16.row.col.f32.f16.f16.f32 "
        "{%0,%1,%2,%3}, {%4,%5,%6,%7}, {%8,%9}, {%0,%1,%2,%3};"
        : "+f"(c[0]), "+f"(c[1]), "+f"(c[2]), "+f"(c[3])
        : "r"(a[0]), "r"(a[1]), "r"(a[2]), "r"(a[3]), "r"(b0), "r"(b1));
}

// ---------------------------------------------------------------------------
// K0: convert E_ent (fp32) into scaled fp16.
// 4 independent float4 per thread (MLP=4) to hide DRAM latency; 12500 blocks.
// ---------------------------------------------------------------------------
__global__ __launch_bounds__(256) void k0_cvtE(const float* __restrict__ E)
{
    const int tid = threadIdx.x;
    const size_t blk = (size_t)blockIdx.x * 4096;   // floats per block
    float4 v[4];
#pragma unroll
    for (int u = 0; u < 4; u++)
        v[u] = *(const float4*)(E + blk + (u * 256 + tid) * 4);
#pragma unroll
    for (int u = 0; u < 4; u++) {
        __half2* p = (__half2*)(g_Ef + blk + (u * 256 + tid) * 4);
        p[0] = __floats2half2_rn(v[u].x * SCALE_E, v[u].y * SCALE_E);
        p[1] = __floats2half2_rn(v[u].z * SCALE_E, v[u].w * SCALE_E);
    }
}

// ---------------------------------------------------------------------------
// K1: split-K (4-way) partial of w0/w1. Block = (batch-group, j-quarter).
// ---------------------------------------------------------------------------
#define K1_ROWS 4
#define K1_J (TWO_R / K1_SPLIT)   // 128
__global__ __launch_bounds__(256) void k1_wproj(
    const int* __restrict__ x,
    const float* __restrict__ E_ent, const float* __restrict__ E_rel,
    const float* __restrict__ W0, const float* __restrict__ W1,
    const float* __restrict__ bw0, const float* __restrict__ bw1)
{
    const int bid = blockIdx.x;
    const int split = bid & (K1_SPLIT - 1);
    const int b0 = (bid >> 2) * K1_ROWS;
    const int tid = threadIdx.x;

    __shared__ float t0s[K1_ROWS][K1_J];
    __shared__ float t1s[K1_ROWS][K1_J];

    const int src = split >> 1;          // 0 -> lhs (E_ent), 1 -> rel (E_rel)
    const int off = (split & 1) * K1_J;  // 0 or 128 within the rank half
    for (int rr = 0; rr < K1_ROWS; rr++) {
        const int b = b0 + rr;
        const size_t row_idx = (size_t)x[b * 3 + src];
        const float* row = (src == 0 ? E_ent : E_rel) + row_idx * TWO_R;
        if (tid < K1_J) t0s[rr][tid] = row[off + tid];
        else            t1s[rr][tid - K1_J] = row[RANK + off + (tid - K1_J)];
    }
    __syncthreads();

    const int k = tid;
    float a0[K1_ROWS], a1[K1_ROWS];
#pragma unroll
    for (int rr = 0; rr < K1_ROWS; rr++) { a0[rr] = 0.f; a1[rr] = 0.f; }

#pragma unroll 8
    for (int j = 0; j < K1_J; j++) {
        const int jj = split * K1_J + j;
        const float w0jk = W0[jj * RANK + k];
        const float w1jk = W1[jj * RANK + k];
#pragma unroll
        for (int rr = 0; rr < K1_ROWS; rr++) {
            const float a = t0s[rr][j];
            const float c = t1s[rr][j];
            a0[rr] += a * w0jk - c * w1jk;
            a1[rr] += a * w1jk + c * w0jk;
        }
    }
    const float b0k = split == 0 ? bw0[k] : 0.f;
    const float b1k = split == 0 ? bw1[k] : 0.f;
#pragma unroll
    for (int rr = 0; rr < K1_ROWS; rr++) {
        g_w0[split * BR + (b0 + rr) * RANK + k] = a0[rr] + b0k;
        g_w1[split * BR + (b0 + rr) * RANK + k] = a1[rr] + b1k;
    }
}

// ---------------------------------------------------------------------------
// K2: logits over 50 neighbors, softmax, ec0/ec1 weighted sums.
// ---------------------------------------------------------------------------
#define K2_SMEM (MAX_NB * TWO_R * 4)   // 102400
__global__ __launch_bounds__(256) void k2_attn(
    const int* __restrict__ nb_idx, const float* __restrict__ E_ent)
{
    extern __shared__ __align__(16) float nbs[];   // [MAX_NB][TWO_R]
    __shared__ float w0s[RANK], w1s[RANK];
    __shared__ float logit_s[MAX_NB];
    __shared__ float alpha_s[MAX_NB];
    __shared__ int   idx_s[MAX_NB];

    const int b = blockIdx.x;
    const int tid = threadIdx.x;
    const int wid = tid >> 5;
    const int lane = tid & 31;

    {
        const int ik = b * RANK + tid;
        w0s[tid] = (g_w0[ik] + g_w0[BR + ik]) + (g_w0[2 * BR + ik] + g_w0[3 * BR + ik]);
        w1s[tid] = (g_w1[ik] + g_w1[BR + ik]) + (g_w1[2 * BR + ik] + g_w1[3 * BR + ik]);
    }
    if (tid < MAX_NB) idx_s[tid] = nb_idx[b * MAX_NB + tid];
    __syncthreads();

    const uint32_t nbs_u = smem_to_u32(nbs);
    for (int u = tid; u < MAX_NB * 128; u += 256) {
        const int m = u >> 7;
        const int q = u & 127;
        CP_ASYNC16(nbs_u + (uint32_t)u * 16,
                   E_ent + (size_t)idx_s[m] * TWO_R + q * 4);
    }
    CP_ASYNC_COMMIT();
    CP_ASYNC_WAIT_GROUP(0);
    __syncthreads();

    for (int m = wid; m < MAX_NB; m += 8) {
        const float* row = nbs + m * TWO_R;
        float s = 0.f;
#pragma unroll
        for (int k = lane; k < RANK; k += 32)
            s += w0s[k] * row[k] - w1s[k] * row[RANK + k];
#pragma unroll
        for (int o = 16; o > 0; o >>= 1) s += __shfl_xor_sync(0xffffffffu, s, o);
        if (lane == 0) logit_s[m] = s;
    }
    __syncthreads();

    if (tid == 0) {
        float mx = logit_s[0];
        for (int m = 1; m < MAX_NB; m++) mx = fmaxf(mx, logit_s[m]);
        float sum = 0.f;
        for (int m = 0; m < MAX_NB; m++) { float e = __expf(logit_s[m] - mx); alpha_s[m] = e; sum += e; }
        const float inv = 1.0f / sum;
        for (int m = 0; m < MAX_NB; m++) alpha_s[m] *= inv;
    }
    __syncthreads();

    const int k = tid;
    float acc0 = 0.f, acc1 = 0.f;
#pragma unroll 10
    for (int m = 0; m < MAX_NB; m++) {
        const float a = alpha_s[m];
        acc0 += a * nbs[m * TWO_R + k];
        acc1 += a * nbs[m * TWO_R + RANK + k];
    }
    g_ec0[b * RANK + k] = acc0;
    g_ec1[b * RANK + k] = acc1;
}

// ---------------------------------------------------------------------------
// K3a: split-K (8-way) partial of ec projection, 8 rows/block.
// 1024 blocks of 32 j-iters; halved W2 L2 traffic vs ROWS=4, 16 FMA chains.
// ---------------------------------------------------------------------------
#define K3_ROWS 8
#define K3_J (RANK / K3_SPLIT)   // 32
__global__ __launch_bounds__(256) void k3a_ecproj(
    const float* __restrict__ W20, const float* __restrict__ W21,
    const float* __restrict__ bw20, const float* __restrict__ bw21)
{
    const int bid = blockIdx.x;
    const int split = bid & (K3_SPLIT - 1);
    const int b0 = (bid >> 3) * K3_ROWS;
    const int tid = threadIdx.x;

    __shared__ float e0s[K3_ROWS][K3_J];
    __shared__ float e1s[K3_ROWS][K3_J];

    // load 2 arrays x 8 rows x 32 cols = 512 values with 256 threads
#pragma unroll
    for (int v = tid; v < 2 * K3_ROWS * K3_J; v += 256) {
        const int arr = v >> 8;            // 0 -> e0, 1 -> e1
        const int rem = v & 255;
        const int rr  = rem >> 5;
        const int j   = rem & 31;
        const float val = (arr == 0 ? g_ec0 : g_ec1)[(b0 + rr) * RANK + split * K3_J + j];
        if (arr == 0) e0s[rr][j] = val; else e1s[rr][j] = val;
    }
    __syncthreads();

    const int k = tid;
    float a0[K3_ROWS], a1[K3_ROWS];
#pragma unroll
    for (int rr = 0; rr < K3_ROWS; rr++) { a0[rr] = 0.f; a1[rr] = 0.f; }

#pragma unroll 4
    for (int j = 0; j < K3_J; j++) {
        const int jj = split * K3_J + j;
        const float w20 = W20[jj * RANK + k];
        const float w21 = W21[jj * RANK + k];
#pragma unroll
        for (int rr = 0; rr < K3_ROWS; rr++) {
            const float a = e0s[rr][j];
            const float c = e1s[rr][j];
            a0[rr] += a * w20 - c * w21;
            a1[rr] += a * w21 + c * w20;
        }
    }
    const float b20 = split == 0 ? bw20[k] : 0.f;
    const float b21 = split == 0 ? bw21[k] : 0.f;
#pragma unroll
    for (int rr = 0; rr < K3_ROWS; rr++) {
        g_en0[split * BR + (b0 + rr) * RANK + k] = a0[rr] + b20;
        g_en1[split * BR + (b0 + rr) * RANK + k] = a1[rr] + b21;
    }
}

// ---------------------------------------------------------------------------
// K3b: gate scalar, gec, q_re/q_im (scaled fp16 into g_Qf), norms.
// Combines the eight k3a split-K partials while loading en.
// ---------------------------------------------------------------------------
__global__ __launch_bounds__(256) void k3b_gate_q(
    const int* __restrict__ x,
    const float* __restrict__ E_ent, const float* __restrict__ E_rel,
    const float* __restrict__ Uo0, const float* __restrict__ Uo1,
    const float* __restrict__ Wo0, const float* __restrict__ b_g,
    float* __restrict__ out)
{
    __shared__ float warp_part[8];
    __shared__ float g_sh2;
    const int b = blockIdx.x;
    const int k = threadIdx.x;
    const int wid = k >> 5, lane = k & 31;

    const size_t lhs = (size_t)x[b * 3 + 0];
    const size_t rel = (size_t)x[b * 3 + 1];
    const size_t rhs = (size_t)x[b * 3 + 2];

    const float l0 = E_ent[lhs * TWO_R + k];
    const float l1 = E_ent[lhs * TWO_R + RANK + k];
    const float r0 = E_rel[rel * TWO_R + k];
    const float r1 = E_rel[rel * TWO_R + RANK + k];
    const float o0 = E_ent[rhs * TWO_R + k];
    const float o1 = E_ent[rhs * TWO_R + RANK + k];

    const int ik = b * RANK + k;
    float en0 = 0.f, en1 = 0.f;
#pragma unroll
    for (int s = 0; s < K3_SPLIT; s++) {
        en0 += g_en0[s * BR + ik];
        en1 += g_en1[s * BR + ik];
    }

    const float sr = l0 * r0 - l1 * r1;
    const float si = l1 * r0 + l0 * r1;

    float p = sr * Uo0[k] - si * Uo1[k] + en0 * Wo0[k];
#pragma unroll
    for (int o = 16; o > 0; o >>= 1) p += __shfl_xor_sync(0xffffffffu, p, o);
    if (lane == 0) warp_part[wid] = p;
    __syncthreads();
    if (k == 0) {
        float tot = 0.f;
#pragma unroll
        for (int w = 0; w < 8; w++) tot += warp_part[w];
        tot += b_g[0];
        g_sh2 = 1.0f / (1.0f + __expf(-tot));
    }
    __syncthreads();
    const float g = g_sh2;

    const float gec0 = g * en0 + (1.0f - g);
    const float gec1 = g * en1;

    const float q_re = sr * gec0 + si * gec1;
    const float q_im = si * gec0 - sr * gec1;

    g_Qf[b * TWO_R + k]        = __float2half_rn(q_re * SCALE_Q);
    g_Qf[b * TWO_R + RANK + k] = __float2half_rn(q_im * SCALE_Q);

    const size_t nk = (size_t)b * RANK + k;
    out[OFF_NLHS + nk] = sqrtf(l0 * l0 + l1 * l1);
    out[OFF_NREL + nk] = sqrtf(r0 * r0 + r1 * r1);
    out[OFF_NRHS + nk] = sqrtf(o0 * o0 + o1 * o1);
    out[OFF_NGEC + nk] = sqrtf(gec0 * gec0 + gec1 * gec1);
}

// ---------------------------------------------------------------------------
// K4: scores = Qf (1024x512) @ Ef^T (512x100000), single scaled-fp16 GEMM on
// mma.sync.m16n8k16. Persistent CTAs, continuous cp.async chunk stream,
// 3-stage pipeline, wait_group(1) (R13-proven configuration).
// ---------------------------------------------------------------------------
#define NCHUNK 8
#define NTILE_M (BATCH / 128)                 // 8
#define NTILE_N ((N_ENT + 255) / 256)         // 391
#define NTILES  (NTILE_M * NTILE_N)           // 3128
#define ROW_B    144                   // 128B data + 16B pad
#define A_TILE_B (128 * ROW_B)         // 18432
#define B_TILE_B (256 * ROW_B)         // 36864
#define STAGE_B  (A_TILE_B + B_TILE_B) // 55296
#define NSTAGE   3
#define SMEM_K4  (NSTAGE * STAGE_B)    // 165888
#define K4_THREADS 256

// Issue loads for global stream position p (tile = own-tile p>>3, chunk p&7)
__device__ __forceinline__ void k4_load_pos(
    uint32_t sbase, int p, int stg, int bidx, int gridx,
    const __half* Qf, const __half* Ef, int tid)
{
    const int T = bidx + (p >> 3) * gridx;
    const int chunk = p & 7;
    const int m0 = (T & (NTILE_M - 1)) * 128;
    const int n0 = (T / NTILE_M) * 256;
    const int k0 = chunk * 64;
    const uint32_t sb = sbase + (uint32_t)stg * STAGE_B;
    // A tile: 128 rows x 8 x 16B = 1024 transfers
#pragma unroll
    for (int u = 0; u < 4; u++) {
        const int idx = tid + u * K4_THREADS;   // 0..1023
        const int row = idx >> 3;
        const int g   = idx & 7;
        const uint32_t soff = sb + (uint32_t)(row * ROW_B + g * 16);
        CP_ASYNC16(soff, Qf + (size_t)(m0 + row) * TWO_R + k0 + g * 8);
    }
    // B tile: 256 rows x 8 x 16B = 2048 transfers
#pragma unroll
    for (int u = 0; u < 8; u++) {
        const int idx = tid + u * K4_THREADS;   // 0..2047
        const int row = idx >> 3;
        const int g   = idx & 7;
        int er = n0 + row; if (er >= N_ENT) er = N_ENT - 1;
        const uint32_t soff = sb + (uint32_t)(A_TILE_B + row * ROW_B + g * 16);
        CP_ASYNC16(soff, Ef + (size_t)er * TWO_R + k0 + g * 8);
    }
}

__global__ __launch_bounds__(K4_THREADS, 1) void k4_hmma(
    const __half* __restrict__ Qf, const __half* __restrict__ Ef,
    float* __restrict__ C)
{
    extern __shared__ __align__(1024) char smem[];
    const uint32_t sbase = smem_to_u32(smem);
    const int tid  = threadIdx.x;
    const int wid  = tid >> 5;
    const int lane = tid & 31;
    const int wm   = wid & 1;       // 0..1 -> 64-row slice
    const int wn   = wid >> 1;      // 0..3 -> 64-col slice
    const int bidx = blockIdx.x;
    const int gridx = gridDim.x;

    const int ntiles_own = (NTILES - bidx + gridx - 1) / gridx;
    const int pmax = ntiles_own * NCHUNK;

    const int laneRow = ((lane >> 3) & 1) * 8 + (lane & 7);
    const int laneG   = lane >> 4;
    const int rowAbase = wm * 64 + laneRow;
    const int rowBbase = wn * 64 + laneRow;

    // preload stream positions 0 and 1
    k4_load_pos(sbase, 0, 0, bidx, gridx, Qf, Ef, tid);
    CP_ASYNC_COMMIT();
    if (pmax > 1) k4_load_pos(sbase, 1, 1, bidx, gridx, Qf, Ef, tid);
    CP_ASYNC_COMMIT();

    int p_load = 2;
    int stg_load = 2;
    int stg = 0;

#pragma unroll 1
    for (int j = 0; j < ntiles_own; j++) {
        const int T = bidx + j * gridx;
        const int m0 = (T & (NTILE_M - 1)) * 128;
        const int n0 = (T / NTILE_M) * 256;

        float acc[4][8][4];
#pragma unroll
        for (int a = 0; a < 4; a++)
#pragma unroll
            for (int b = 0; b < 8; b++)
#pragma unroll
                for (int c = 0; c < 4; c++) acc[a][b][c] = 0.f;

#pragma unroll 1
        for (int i = 0; i < NCHUNK; i++) {
            CP_ASYNC_WAIT_GROUP(1);
            __syncthreads();

            if (p_load < pmax)
                k4_load_pos(sbase, p_load, stg_load, bidx, gridx, Qf, Ef, tid);
            CP_ASYNC_COMMIT();
            p_load++;
            stg_load = stg_load + 1; if (stg_load >= NSTAGE) stg_load = 0;

            const uint32_t sA = sbase + (uint32_t)stg * STAGE_B;
            const uint32_t sB = sA + A_TILE_B;

#pragma unroll
            for (int kh = 0; kh < 4; kh++) {
                const uint32_t gof = (uint32_t)(kh * 32 + laneG * 16);

                uint32_t a_op[4][4], b_op[4][4];
#pragma unroll
                for (int mt = 0; mt < 4; mt++)
                    ldsm_x4(a_op[mt], sA + (uint32_t)((rowAbase + mt * 16) * ROW_B) + gof);
#pragma unroll
                for (int q = 0; q < 4; q++)
                    ldsm_x4(b_op[q], sB + (uint32_t)((rowBbase + q * 16) * ROW_B) + gof);

#pragma unroll
                for (int mt = 0; mt < 4; mt++)
#pragma unroll
                    for (int jj = 0; jj < 8; jj++)
                        mma_16816_f16(acc[mt][jj], a_op[mt],
                                      b_op[jj >> 1][jj & 1], b_op[jj >> 1][2 + (jj & 1)]);
            }

            stg = stg + 1; if (stg >= NSTAGE) stg = 0;
        }

        // Epilogue (overlaps with next tile's in-flight cp.async loads)
        const int erow = (lane >> 2);
        const int ecol = (lane & 3) * 2;
#pragma unroll
        for (int mt = 0; mt < 4; mt++) {
            const int r1 = m0 + wm * 64 + mt * 16 + erow;
#pragma unroll
            for (int jj = 0; jj < 8; jj++) {
                const int n = n0 + wn * 64 + jj * 8 + ecol;
                if (n < N_ENT) {
                    float2 v01 = make_float2(acc[mt][jj][0] * SCALE_OUT,
                                             acc[mt][jj][1] * SCALE_OUT);
                    float2 v23 = make_float2(acc[mt][jj][2] * SCALE_OUT,
                                             acc[mt][jj][3] * SCALE_OUT);
                    *(float2*)(C + (size_t)r1 * N_ENT + n) = v01;
                    *(float2*)(C + (size_t)(r1 + 8) * N_ENT + n) = v23;
                }
            }
        }
    }
}

// ---------------------------------------------------------------------------
extern "C" void kernel_launch(void* const* d_in, const int* in_sizes, int n_in,
                              void* d_out, int out_size)
{
    const int*   x      = (const int*)  d_in[0];
    const int*   nb_idx = (const int*)  d_in[1];
    const float* E_ent  = (const float*)d_in[2];
    const float* E_rel  = (const float*)d_in[3];
    const float* W0     = (const float*)d_in[4];
    const float* W1     = (const float*)d_in[5];
    const float* bw0    = (const float*)d_in[6];
    const float* bw1    = (const float*)d_in[7];
    const float* W20    = (const float*)d_in[8];
    const float* W21    = (const float*)d_in[9];
    const float* bw20   = (const float*)d_in[10];
    const float* bw21   = (const float*)d_in[11];
    const float* Uo0    = (const float*)d_in[12];
    const float* Uo1    = (const float*)d_in[13];
    const float* Wo0    = (const float*)d_in[14];
    const float* b_g    = (const float*)d_in[15];
    float* out = (float*)d_out;

    __half *Qf, *Ef;
    cudaGetSymbolAddress((void**)&Qf, g_Qf);
    cudaGetSymbolAddress((void**)&Ef, g_Ef);

    cudaFuncSetAttribute(k4_hmma, cudaFuncAttributeMaxDynamicSharedMemorySize, SMEM_K4);
    cudaFuncSetAttribute(k2_attn, cudaFuncAttributeMaxDynamicSharedMemorySize, K2_SMEM);

    int nsm = 148;
    cudaDeviceGetAttribute(&nsm, cudaDevAttrMultiProcessorCount, 0);

    // 51.2M floats / 4096 per block = 12500 blocks
    k0_cvtE<<<12500, 256>>>(E_ent);

    k1_wproj  <<<(BATCH / K1_ROWS) * K1_SPLIT, 256>>>(x, E_ent, E_rel, W0, W1, bw0, bw1);
    k2_attn   <<<BATCH, 256, K2_SMEM>>>(nb_idx, E_ent);
    k3a_ecproj<<<(BATCH / K3_ROWS) * K3_SPLIT, 256>>>(W20, W21, bw20, bw21);
    k3b_gate_q<<<BATCH, 256>>>(x, E_ent, E_rel, Uo0, Uo1, Wo0, b_g, out);

    k4_hmma<<<nsm, K4_THREADS, SMEM_K4>>>(Qf, Ef, out + OFF_SCORES);
}